// round 5
// baseline (speedup 1.0000x reference)
#include <cuda_runtime.h>

#define NN 200000
#define DD 16
#define KK 16
#define FF 33
#define GN_EPS 1e-5f
#define SLOPE 0.2f

// Device globals (no allocation allowed)
__device__ float g_buf0[NN * DD];
__device__ float g_buf1[NN * DD];
__device__ int   g_idx32[NN * KK];
__device__ int   g_is64;

// Detect whether idx buffer is int64 or int32 (jax may silently downcast).
__global__ void detect_idx_kernel(const long long* __restrict__ p) {
    int ok = 1;
#pragma unroll 1
    for (int i = 0; i < 32; i++) {
        long long v = p[i];
        if (v < 0 || v >= NN) ok = 0;
    }
    g_is64 = ok;
}

// Convert idx to int32 once; reused by all 3 layers.
__global__ __launch_bounds__(256) void convert_idx_kernel(const void* __restrict__ idxv) {
    int i = blockIdx.x * 256 + threadIdx.x;
    if (i >= NN * KK) return;
    long long v = g_is64 ? ((const long long*)idxv)[i]
                         : (long long)((const int*)idxv)[i];
    g_idx32[i] = (int)v;
}

__device__ __forceinline__ float leaky(float x) {
    return fmaf(SLOPE, fminf(x, 0.0f), fmaxf(x, 0.0f));
}

__device__ __forceinline__ void loadrow16(float* dst, const float* __restrict__ src) {
    const float4* p = reinterpret_cast<const float4*>(src);
    float4 a = p[0], b = p[1], c = p[2], d = p[3];
    dst[0]  = a.x; dst[1]  = a.y; dst[2]  = a.z; dst[3]  = a.w;
    dst[4]  = b.x; dst[5]  = b.y; dst[6]  = b.z; dst[7]  = b.w;
    dst[8]  = c.x; dst[9]  = c.y; dst[10] = c.z; dst[11] = c.w;
    dst[12] = d.x; dst[13] = d.y; dst[14] = d.z; dst[15] = d.w;
}

// 4 lanes per node; lane t owns g = t + 4*i, i in [0,9).
__global__ __launch_bounds__(128, 6) void layer_kernel(
    const float* __restrict__ in_feat,   // [NN, DD]
    const float* __restrict__ dists,     // [NN, KK]
    const int*   __restrict__ idx32,     // [NN, KK]
    const float* __restrict__ W1,        // [FF, FF]
    const float* __restrict__ b1,        // [FF]
    const float* __restrict__ W2,        // [FF, DD]
    const float* __restrict__ b2,        // [DD]
    const float* __restrict__ gnw,       // [DD]
    const float* __restrict__ gnb,       // [DD]
    float* __restrict__ out_feat)        // [NN, DD]
{
    // W1 transposed [g][f], padded to 36 rows / stride 36 (lanes hit banks +4t)
    __shared__ float sW1T[36][36];
    // W2 [g][d], stride 20 (lanes hit banks {0,20,8,28})
    __shared__ float sW2p[36 * 20];
    __shared__ float sb1[36];
    __shared__ float sb2[DD], sgnw[DD], sgnb[DD];

    // Zero (padding rows must contribute exactly 0)
    for (int i = threadIdx.x; i < 36 * 36; i += 128) ((float*)sW1T)[i] = 0.0f;
    for (int i = threadIdx.x; i < 36 * 20; i += 128) sW2p[i] = 0.0f;
    if (threadIdx.x < 36) sb1[threadIdx.x] = 0.0f;
    __syncthreads();
    for (int i = threadIdx.x; i < FF * FF; i += 128) {
        int f = i / FF, g = i % FF;
        sW1T[g][f] = W1[i];
    }
    for (int i = threadIdx.x; i < FF * DD; i += 128) {
        sW2p[(i / DD) * 20 + (i % DD)] = W2[i];
    }
    if (threadIdx.x < FF) sb1[threadIdx.x] = b1[threadIdx.x];
    if (threadIdx.x < DD) {
        sb2[threadIdx.x]  = b2[threadIdx.x];
        sgnw[threadIdx.x] = gnw[threadIdx.x];
        sgnb[threadIdx.x] = gnb[threadIdx.x];
    }
    __syncthreads();

    int gt = blockIdx.x * 128 + threadIdx.x;
    int n  = gt >> 2;
    int t  = threadIdx.x & 3;
    if (n >= NN) return;

    const float* frow = in_feat + (size_t)n * DD;
    const int*   irow = idx32   + (size_t)n * KK;
    const float* drow = dists   + (size_t)n * KK;

    // sw[i] = b1[g] + self . W1[0:16][g]   for g = t + 4i  (k-invariant)
    float sw[9];
    {
        float sf[16];
        loadrow16(sf, frow);
#pragma unroll
        for (int i = 0; i < 9; i++) {
            int g = t + 4 * i;
            const float4* wr = reinterpret_cast<const float4*>(&sW1T[g][0]);
            float4 w0 = wr[0], w1 = wr[1], w2 = wr[2], w3 = wr[3];
            float acc = sb1[g];
            acc += sf[0]  * w0.x + sf[1]  * w0.y + sf[2]  * w0.z + sf[3]  * w0.w;
            acc += sf[4]  * w1.x + sf[5]  * w1.y + sf[6]  * w1.z + sf[7]  * w1.w;
            acc += sf[8]  * w2.x + sf[9]  * w2.y + sf[10] * w2.z + sf[11] * w2.w;
            acc += sf[12] * w3.x + sf[13] * w3.y + sf[14] * w3.z + sf[15] * w3.w;
            sw[i] = acc;
        }
    }

    float msg[16];
#pragma unroll
    for (int d = 0; d < 16; d++) msg[d] = 0.0f;

    // Per-neighbor body: h[g] = leaky(sw + nb.W1[16:32][g] + dk*W1[32][g]); msg += h*W2[g]
    auto body = [&](int k, const float* nb) {
        float dk = drow[k];
#pragma unroll
        for (int i = 0; i < 9; i++) {
            int g = t + 4 * i;
            const float4* wr = reinterpret_cast<const float4*>(&sW1T[g][16]);
            float4 w0 = wr[0], w1 = wr[1], w2 = wr[2], w3 = wr[3];
            float acc = fmaf(dk, sW1T[g][32], sw[i]);
            acc += nb[0]  * w0.x + nb[1]  * w0.y + nb[2]  * w0.z + nb[3]  * w0.w;
            acc += nb[4]  * w1.x + nb[5]  * w1.y + nb[6]  * w1.z + nb[7]  * w1.w;
            acc += nb[8]  * w2.x + nb[9]  * w2.y + nb[10] * w2.z + nb[11] * w2.w;
            acc += nb[12] * w3.x + nb[13] * w3.y + nb[14] * w3.z + nb[15] * w3.w;
            float hg = leaky(acc);
            const float4* ar = reinterpret_cast<const float4*>(&sW2p[g * 20]);
            float4 a0 = ar[0], a1 = ar[1], a2 = ar[2], a3 = ar[3];
            msg[0]  = fmaf(hg, a0.x, msg[0]);  msg[1]  = fmaf(hg, a0.y, msg[1]);
            msg[2]  = fmaf(hg, a0.z, msg[2]);  msg[3]  = fmaf(hg, a0.w, msg[3]);
            msg[4]  = fmaf(hg, a1.x, msg[4]);  msg[5]  = fmaf(hg, a1.y, msg[5]);
            msg[6]  = fmaf(hg, a1.z, msg[6]);  msg[7]  = fmaf(hg, a1.w, msg[7]);
            msg[8]  = fmaf(hg, a2.x, msg[8]);  msg[9]  = fmaf(hg, a2.y, msg[9]);
            msg[10] = fmaf(hg, a2.z, msg[10]); msg[11] = fmaf(hg, a2.w, msg[11]);
            msg[12] = fmaf(hg, a3.x, msg[12]); msg[13] = fmaf(hg, a3.y, msg[13]);
            msg[14] = fmaf(hg, a3.z, msg[14]); msg[15] = fmaf(hg, a3.w, msg[15]);
        }
    };

    // Software-pipelined gather: prefetch next neighbor row while computing current.
    float nbA[16], nbB[16];
    {
        int j0 = irow[0];
        loadrow16(nbA, in_feat + (size_t)j0 * DD);
    }
#pragma unroll 1
    for (int kk = 0; kk < KK; kk += 2) {
        {
            int j = irow[kk + 1];
            loadrow16(nbB, in_feat + (size_t)j * DD);
        }
        body(kk, nbA);
        if (kk + 2 < KK) {
            int j = irow[kk + 2];
            loadrow16(nbA, in_feat + (size_t)j * DD);
        }
        body(kk + 1, nbB);
    }

    // Reduce partial msg across the 4 lanes of this node, then add K*b2.
#pragma unroll
    for (int d = 0; d < 16; d++) {
        msg[d] += __shfl_xor_sync(0xffffffffu, msg[d], 1);
        msg[d] += __shfl_xor_sync(0xffffffffu, msg[d], 2);
        msg[d] = fmaf((float)KK, sb2[d], msg[d]);
    }

    // GroupNorm (2 groups of 8) + leaky + residual (computed redundantly per lane)
    float o[16];
#pragma unroll
    for (int grp = 0; grp < 2; grp++) {
        float mu = 0.0f, m2 = 0.0f;
#pragma unroll
        for (int c = 0; c < 8; c++) {
            float v = msg[grp * 8 + c];
            mu += v;
            m2 += v * v;
        }
        mu *= 0.125f;
        float var = m2 * 0.125f - mu * mu;
        float inv = rsqrtf(var + GN_EPS);
#pragma unroll
        for (int c = 0; c < 8; c++) {
            int d = grp * 8 + c;
            float xn = (msg[d] - mu) * inv;
            o[d] = leaky(xn * sgnw[d] + sgnb[d]);
        }
    }
    // residual (reload self row; L2-hot)
    {
        const float4* p = reinterpret_cast<const float4*>(frow);
        float4 a = p[0], b = p[1], c = p[2], d = p[3];
        o[0]  += a.x; o[1]  += a.y; o[2]  += a.z; o[3]  += a.w;
        o[4]  += b.x; o[5]  += b.y; o[6]  += b.z; o[7]  += b.w;
        o[8]  += c.x; o[9]  += c.y; o[10] += c.z; o[11] += c.w;
        o[12] += d.x; o[13] += d.y; o[14] += d.z; o[15] += d.w;
    }

    // Each lane stores its own quarter of the output row.
    float4* orow = reinterpret_cast<float4*>(out_feat + (size_t)n * DD);
    if (t == 0)      orow[0] = make_float4(o[0],  o[1],  o[2],  o[3]);
    else if (t == 1) orow[1] = make_float4(o[4],  o[5],  o[6],  o[7]);
    else if (t == 2) orow[2] = make_float4(o[8],  o[9],  o[10], o[11]);
    else             orow[3] = make_float4(o[12], o[13], o[14], o[15]);
}

extern "C" void kernel_launch(void* const* d_in, const int* in_sizes, int n_in,
                              void* d_out, int out_size) {
    const float* y     = (const float*)d_in[0];
    const float* dists = (const float*)d_in[1];
    const float* W1    = (const float*)d_in[2];
    const float* b1    = (const float*)d_in[3];
    const float* W2    = (const float*)d_in[4];
    const float* b2    = (const float*)d_in[5];
    const float* gnw   = (const float*)d_in[6];
    const float* gnb   = (const float*)d_in[7];
    const void*  idx   = (const void*)d_in[8];
    float* out = (float*)d_out;

    float *buf0, *buf1;
    int* idx32;
    cudaGetSymbolAddress((void**)&buf0, g_buf0);
    cudaGetSymbolAddress((void**)&buf1, g_buf1);
    cudaGetSymbolAddress((void**)&idx32, g_idx32);

    detect_idx_kernel<<<1, 1>>>((const long long*)idx);
    convert_idx_kernel<<<(NN * KK + 255) / 256, 256>>>(idx);

    int blocks = (NN * 4 + 127) / 128;
    layer_kernel<<<blocks, 128>>>(y,    dists, idx32, W1,               b1,          W2,               b2,          gnw,          gnb,          buf0);
    layer_kernel<<<blocks, 128>>>(buf0, dists, idx32, W1 + 1 * FF * FF, b1 + 1 * FF, W2 + 1 * FF * DD, b2 + 1 * DD, gnw + 1 * DD, gnb + 1 * DD, buf1);
    layer_kernel<<<blocks, 128>>>(buf1, dists, idx32, W1 + 2 * FF * FF, b1 + 2 * FF, W2 + 2 * FF * DD, b2 + 2 * DD, gnw + 2 * DD, gnb + 2 * DD, out);
}

// round 7
// speedup vs baseline: 1.7535x; 1.7535x over previous
#include <cuda_runtime.h>
#include <cstdint>

#define NN 200000
#define DD 16
#define KK 16
#define FF 33
#define GN_EPS 1e-5f
#define SLOPE 0.2f

#define NPB 32           // nodes per block (128 threads, 4 lanes/node)
#define NSTRIDE 268      // floats per staged node (16*16=256 + 12 pad for banks)

// Device globals (no allocation allowed)
__device__ float g_buf0[NN * DD];
__device__ float g_buf1[NN * DD];
__device__ int   g_idx32[NN * KK];
__device__ int   g_is64;

__global__ void detect_idx_kernel(const long long* __restrict__ p) {
    int ok = 1;
#pragma unroll 1
    for (int i = 0; i < 32; i++) {
        long long v = p[i];
        if (v < 0 || v >= NN) ok = 0;
    }
    g_is64 = ok;
}

__global__ __launch_bounds__(256) void convert_idx_kernel(const void* __restrict__ idxv) {
    int i = blockIdx.x * 256 + threadIdx.x;
    if (i >= NN * KK) return;
    long long v = g_is64 ? ((const long long*)idxv)[i]
                         : (long long)((const int*)idxv)[i];
    g_idx32[i] = (int)v;
}

__device__ __forceinline__ float leaky(float x) {
    return fmaf(SLOPE, fminf(x, 0.0f), fmaxf(x, 0.0f));
}

__device__ __forceinline__ void cp_async16(unsigned int smem_dst, const void* gsrc) {
    asm volatile("cp.async.ca.shared.global [%0], [%1], 16;\n" :: "r"(smem_dst), "l"(gsrc));
}

// 4 lanes per node; lane t owns g = t + 4*i, i in [0,9).
// All 16 neighbor rows of a node are staged into SMEM with cp.async
// (16 concurrent 16B copies per lane -> full-row MLP, no register cost).
__global__ __launch_bounds__(128, 5) void layer_kernel(
    const float* __restrict__ in_feat,   // [NN, DD]
    const float* __restrict__ dists,     // [NN, KK]
    const int*   __restrict__ idx32,     // [NN, KK]
    const float* __restrict__ W1,        // [FF, FF]
    const float* __restrict__ b1,        // [FF]
    const float* __restrict__ W2,        // [FF, DD]
    const float* __restrict__ b2,        // [DD]
    const float* __restrict__ gnw,       // [DD]
    const float* __restrict__ gnb,       // [DD]
    float* __restrict__ out_feat)        // [NN, DD]
{
    __shared__ float snb[NPB * NSTRIDE];           // 34304 B neighbor staging
    __shared__ float sW1T[36][36];                 // W1 transposed [g][f]
    __shared__ float sW2p[36 * 20];                // W2 [g][d], stride 20
    __shared__ float sb1[36];
    __shared__ float sb2[DD], sgnw[DD], sgnb[DD];

    for (int i = threadIdx.x; i < 36 * 36; i += 128) ((float*)sW1T)[i] = 0.0f;
    for (int i = threadIdx.x; i < 36 * 20; i += 128) sW2p[i] = 0.0f;
    if (threadIdx.x < 36) sb1[threadIdx.x] = 0.0f;
    __syncthreads();
    for (int i = threadIdx.x; i < FF * FF; i += 128) {
        int f = i / FF, g = i % FF;
        sW1T[g][f] = W1[i];
    }
    for (int i = threadIdx.x; i < FF * DD; i += 128) {
        sW2p[(i / DD) * 20 + (i % DD)] = W2[i];
    }
    if (threadIdx.x < FF) sb1[threadIdx.x] = b1[threadIdx.x];
    if (threadIdx.x < DD) {
        sb2[threadIdx.x]  = b2[threadIdx.x];
        sgnw[threadIdx.x] = gnw[threadIdx.x];
        sgnb[threadIdx.x] = gnb[threadIdx.x];
    }
    __syncthreads();

    const int tid = threadIdx.x;
    const int nb_ = tid >> 2;            // node within block
    const int t   = tid & 3;             // lane within node quad
    const int n   = blockIdx.x * NPB + nb_;   // grid is exact: n < NN always

    const float* frow = in_feat + (size_t)n * DD;
    const float* drow = dists   + (size_t)n * KK;

    // ---- Stage ALL 16 neighbor rows concurrently (lane t loads quarter t) ----
    unsigned int sdst;
    {
        const float* base = &snb[nb_ * NSTRIDE];
        sdst = (unsigned int)__cvta_generic_to_shared(base) + (unsigned int)(t * 16);
    }
    {
        const int4* i4 = reinterpret_cast<const int4*>(idx32 + (size_t)n * KK);
        int4 ia = i4[0], ib = i4[1], ic = i4[2], id_ = i4[3];
        int js[16] = {ia.x, ia.y, ia.z, ia.w, ib.x, ib.y, ib.z, ib.w,
                      ic.x, ic.y, ic.z, ic.w, id_.x, id_.y, id_.z, id_.w};
#pragma unroll
        for (int r = 0; r < 16; r++) {
            cp_async16(sdst + (unsigned int)(r * 64),
                       in_feat + (size_t)js[r] * DD + t * 4);
        }
    }

    // ---- Overlap: k-invariant self contribution while gathers fly ----
    float sw[9];
    {
        float sf[16];
        const float4* p = reinterpret_cast<const float4*>(frow);
        float4 a = p[0], b = p[1], c = p[2], d = p[3];
        sf[0]  = a.x; sf[1]  = a.y; sf[2]  = a.z; sf[3]  = a.w;
        sf[4]  = b.x; sf[5]  = b.y; sf[6]  = b.z; sf[7]  = b.w;
        sf[8]  = c.x; sf[9]  = c.y; sf[10] = c.z; sf[11] = c.w;
        sf[12] = d.x; sf[13] = d.y; sf[14] = d.z; sf[15] = d.w;
#pragma unroll
        for (int i = 0; i < 9; i++) {
            int g = t + 4 * i;
            const float4* wr = reinterpret_cast<const float4*>(&sW1T[g][0]);
            float4 w0 = wr[0], w1 = wr[1], w2 = wr[2], w3 = wr[3];
            float acc = sb1[g];
            acc += sf[0]  * w0.x + sf[1]  * w0.y + sf[2]  * w0.z + sf[3]  * w0.w;
            acc += sf[4]  * w1.x + sf[5]  * w1.y + sf[6]  * w1.z + sf[7]  * w1.w;
            acc += sf[8]  * w2.x + sf[9]  * w2.y + sf[10] * w2.z + sf[11] * w2.w;
            acc += sf[12] * w3.x + sf[13] * w3.y + sf[14] * w3.z + sf[15] * w3.w;
            sw[i] = acc;
        }
    }

    asm volatile("cp.async.wait_all;\n" ::: "memory");
    __syncwarp();

    float msg[16];
#pragma unroll
    for (int d = 0; d < 16; d++) msg[d] = 0.0f;

    const float* nodebuf = &snb[nb_ * NSTRIDE];

#pragma unroll 1
    for (int k = 0; k < KK; k++) {
        float nb[16];
        {
            const float4* row = reinterpret_cast<const float4*>(nodebuf + k * 16);
            float4 a = row[0], b = row[1], c = row[2], d = row[3];
            nb[0]  = a.x; nb[1]  = a.y; nb[2]  = a.z; nb[3]  = a.w;
            nb[4]  = b.x; nb[5]  = b.y; nb[6]  = b.z; nb[7]  = b.w;
            nb[8]  = c.x; nb[9]  = c.y; nb[10] = c.z; nb[11] = c.w;
            nb[12] = d.x; nb[13] = d.y; nb[14] = d.z; nb[15] = d.w;
        }
        float dk = drow[k];
#pragma unroll
        for (int i = 0; i < 9; i++) {
            int g = t + 4 * i;
            const float4* wr = reinterpret_cast<const float4*>(&sW1T[g][16]);
            float4 w0 = wr[0], w1 = wr[1], w2 = wr[2], w3 = wr[3];
            float acc = fmaf(dk, sW1T[g][32], sw[i]);
            acc += nb[0]  * w0.x + nb[1]  * w0.y + nb[2]  * w0.z + nb[3]  * w0.w;
            acc += nb[4]  * w1.x + nb[5]  * w1.y + nb[6]  * w1.z + nb[7]  * w1.w;
            acc += nb[8]  * w2.x + nb[9]  * w2.y + nb[10] * w2.z + nb[11] * w2.w;
            acc += nb[12] * w3.x + nb[13] * w3.y + nb[14] * w3.z + nb[15] * w3.w;
            float hg = leaky(acc);
            const float4* ar = reinterpret_cast<const float4*>(&sW2p[g * 20]);
            float4 a0 = ar[0], a1 = ar[1], a2 = ar[2], a3 = ar[3];
            msg[0]  = fmaf(hg, a0.x, msg[0]);  msg[1]  = fmaf(hg, a0.y, msg[1]);
            msg[2]  = fmaf(hg, a0.z, msg[2]);  msg[3]  = fmaf(hg, a0.w, msg[3]);
            msg[4]  = fmaf(hg, a1.x, msg[4]);  msg[5]  = fmaf(hg, a1.y, msg[5]);
            msg[6]  = fmaf(hg, a1.z, msg[6]);  msg[7]  = fmaf(hg, a1.w, msg[7]);
            msg[8]  = fmaf(hg, a2.x, msg[8]);  msg[9]  = fmaf(hg, a2.y, msg[9]);
            msg[10] = fmaf(hg, a2.z, msg[10]); msg[11] = fmaf(hg, a2.w, msg[11]);
            msg[12] = fmaf(hg, a3.x, msg[12]); msg[13] = fmaf(hg, a3.y, msg[13]);
            msg[14] = fmaf(hg, a3.z, msg[14]); msg[15] = fmaf(hg, a3.w, msg[15]);
        }
    }

    // Reduce partial msg across the 4 lanes of this node, then add K*b2.
#pragma unroll
    for (int d = 0; d < 16; d++) {
        msg[d] += __shfl_xor_sync(0xffffffffu, msg[d], 1);
        msg[d] += __shfl_xor_sync(0xffffffffu, msg[d], 2);
        msg[d] = fmaf((float)KK, sb2[d], msg[d]);
    }

    // GroupNorm (2 groups of 8) + leaky + residual
    float o[16];
#pragma unroll
    for (int grp = 0; grp < 2; grp++) {
        float mu = 0.0f, m2 = 0.0f;
#pragma unroll
        for (int c = 0; c < 8; c++) {
            float v = msg[grp * 8 + c];
            mu += v;
            m2 += v * v;
        }
        mu *= 0.125f;
        float var = m2 * 0.125f - mu * mu;
        float inv = rsqrtf(var + GN_EPS);
#pragma unroll
        for (int c = 0; c < 8; c++) {
            int d = grp * 8 + c;
            float xn = (msg[d] - mu) * inv;
            o[d] = leaky(xn * sgnw[d] + sgnb[d]);
        }
    }
    {
        const float4* p = reinterpret_cast<const float4*>(frow);
        float4 a = p[0], b = p[1], c = p[2], d = p[3];
        o[0]  += a.x; o[1]  += a.y; o[2]  += a.z; o[3]  += a.w;
        o[4]  += b.x; o[5]  += b.y; o[6]  += b.z; o[7]  += b.w;
        o[8]  += c.x; o[9]  += c.y; o[10] += c.z; o[11] += c.w;
        o[12] += d.x; o[13] += d.y; o[14] += d.z; o[15] += d.w;
    }

    // Each lane stores its own quarter of the output row.
    float4* orow = reinterpret_cast<float4*>(out_feat + (size_t)n * DD);
    if (t == 0)      orow[0] = make_float4(o[0],  o[1],  o[2],  o[3]);
    else if (t == 1) orow[1] = make_float4(o[4],  o[5],  o[6],  o[7]);
    else if (t == 2) orow[2] = make_float4(o[8],  o[9],  o[10], o[11]);
    else             orow[3] = make_float4(o[12], o[13], o[14], o[15]);
}

extern "C" void kernel_launch(void* const* d_in, const int* in_sizes, int n_in,
                              void* d_out, int out_size) {
    const float* y     = (const float*)d_in[0];
    const float* dists = (const float*)d_in[1];
    const float* W1    = (const float*)d_in[2];
    const float* b1    = (const float*)d_in[3];
    const float* W2    = (const float*)d_in[4];
    const float* b2    = (const float*)d_in[5];
    const float* gnw   = (const float*)d_in[6];
    const float* gnb   = (const float*)d_in[7];
    const void*  idx   = (const void*)d_in[8];
    float* out = (float*)d_out;

    float *buf0, *buf1;
    int* idx32;
    cudaGetSymbolAddress((void**)&buf0, g_buf0);
    cudaGetSymbolAddress((void**)&buf1, g_buf1);
    cudaGetSymbolAddress((void**)&idx32, g_idx32);

    detect_idx_kernel<<<1, 1>>>((const long long*)idx);
    convert_idx_kernel<<<(NN * KK + 255) / 256, 256>>>(idx);

    int blocks = NN / NPB;   // 6250, exact
    layer_kernel<<<blocks, 128>>>(y,    dists, idx32, W1,               b1,          W2,               b2,          gnw,          gnb,          buf0);
    layer_kernel<<<blocks, 128>>>(buf0, dists, idx32, W1 + 1 * FF * FF, b1 + 1 * FF, W2 + 1 * FF * DD, b2 + 1 * DD, gnw + 1 * DD, gnb + 1 * DD, buf1);
    layer_kernel<<<blocks, 128>>>(buf1, dists, idx32, W1 + 2 * FF * FF, b1 + 2 * FF, W2 + 2 * FF * DD, b2 + 2 * DD, gnw + 2 * DD, gnb + 2 * DD, out);
}

// round 8
// speedup vs baseline: 2.5972x; 1.4811x over previous
#include <cuda_runtime.h>
#include <cstdint>

#define NN 200000
#define DD 16
#define KK 16
#define FF 33
#define GN_EPS 1e-5f
#define SLOPE 0.2f

#define NPB 16           // nodes per chunk (64 threads, 4 lanes/node)
#define NSTR 272         // floats per staged node: 256 + 16 (mod 32 == 16 -> conflict-free)
#define NCHUNK (NN / NPB)   // 12500 exact
#define GRIDB 740        // persistent blocks (5 per SM * 148)

// Device globals (no allocation allowed)
__device__ float g_buf0[NN * DD];
__device__ float g_buf1[NN * DD];
__device__ int   g_idx32[NN * KK];
__device__ int   g_is64;

__global__ void detect_idx_kernel(const long long* __restrict__ p) {
    int ok = 1;
#pragma unroll 1
    for (int i = 0; i < 32; i++) {
        long long v = p[i];
        if (v < 0 || v >= NN) ok = 0;
    }
    g_is64 = ok;
}

__global__ __launch_bounds__(256) void convert_idx_kernel(const void* __restrict__ idxv) {
    int i = blockIdx.x * 256 + threadIdx.x;
    if (i >= NN * KK) return;
    long long v = g_is64 ? ((const long long*)idxv)[i]
                         : (long long)((const int*)idxv)[i];
    g_idx32[i] = (int)v;
}

__device__ __forceinline__ float leaky(float x) {
    return fmaf(SLOPE, fminf(x, 0.0f), fmaxf(x, 0.0f));
}

__device__ __forceinline__ void cp_async16(unsigned int smem_dst, const void* gsrc) {
    asm volatile("cp.async.cg.shared.global [%0], [%1], 16;\n" :: "r"(smem_dst), "l"(gsrc));
}
__device__ __forceinline__ void cp_commit() {
    asm volatile("cp.async.commit_group;\n" ::: "memory");
}
__device__ __forceinline__ void cp_wait1() {
    asm volatile("cp.async.wait_group 1;\n" ::: "memory");
}
__device__ __forceinline__ void cp_wait0() {
    asm volatile("cp.async.wait_group 0;\n" ::: "memory");
}

// Persistent kernel: 64 threads/block (16 nodes * 4 lanes), double-buffered
// cp.async staging of all 16 neighbor rows per node; gathers for chunk j+1
// fly while chunk j computes. Lane t of a quad owns g = t + 4i, i in [0,9).
__global__ __launch_bounds__(64) void layer_kernel(
    const float* __restrict__ in_feat,   // [NN, DD]
    const float* __restrict__ dists,     // [NN, KK]
    const int*   __restrict__ idx32,     // [NN, KK]
    const float* __restrict__ W1,        // [FF, FF]
    const float* __restrict__ b1,        // [FF]
    const float* __restrict__ W2,        // [FF, DD]
    const float* __restrict__ b2,        // [DD]
    const float* __restrict__ gnw,       // [DD]
    const float* __restrict__ gnb,       // [DD]
    float* __restrict__ out_feat)        // [NN, DD]
{
    __shared__ float snb[2][NPB * NSTR];           // 2 x 17408 B staging
    __shared__ float sW1T[36][36];                 // W1 transposed [g][f], zero-padded
    __shared__ float sW2p[36 * 20];                // W2 [g][d], stride 20, zero-padded
    __shared__ float sb1[36];
    __shared__ float sb2[DD], sgnw[DD], sgnb[DD];

    for (int i = threadIdx.x; i < 36 * 36; i += 64) ((float*)sW1T)[i] = 0.0f;
    for (int i = threadIdx.x; i < 36 * 20; i += 64) sW2p[i] = 0.0f;
    if (threadIdx.x < 36) sb1[threadIdx.x] = 0.0f;
    __syncthreads();
    for (int i = threadIdx.x; i < FF * FF; i += 64) {
        int f = i / FF, g = i % FF;
        sW1T[g][f] = W1[i];
    }
    for (int i = threadIdx.x; i < FF * DD; i += 64) {
        sW2p[(i / DD) * 20 + (i % DD)] = W2[i];
    }
    if (threadIdx.x < FF) sb1[threadIdx.x] = b1[threadIdx.x];
    if (threadIdx.x < DD) {
        sb2[threadIdx.x]  = b2[threadIdx.x];
        sgnw[threadIdx.x] = gnw[threadIdx.x];
        sgnb[threadIdx.x] = gnb[threadIdx.x];
    }
    __syncthreads();

    const int tid = threadIdx.x;
    const int nb_ = tid >> 2;            // node slot within chunk (0..15)
    const int t   = tid & 3;             // lane within quad

    const unsigned int sbase0 =
        (unsigned int)__cvta_generic_to_shared(&snb[0][nb_ * NSTR]) + (unsigned int)(t * 16);
    const unsigned int sbase1 =
        (unsigned int)__cvta_generic_to_shared(&snb[1][nb_ * NSTR]) + (unsigned int)(t * 16);

    // Stage all 16 neighbor rows of node (chunk*NPB + nb_): lane t copies quarter t.
    auto stage = [&](int chunk, int par) {
        int n = chunk * NPB + nb_;
        unsigned int sdst = par ? sbase1 : sbase0;
        const int4* i4 = reinterpret_cast<const int4*>(idx32 + (size_t)n * KK);
        int4 ia = i4[0], ib = i4[1], ic = i4[2], id_ = i4[3];
        int js[16] = {ia.x, ia.y, ia.z, ia.w, ib.x, ib.y, ib.z, ib.w,
                      ic.x, ic.y, ic.z, ic.w, id_.x, id_.y, id_.z, id_.w};
#pragma unroll
        for (int r = 0; r < 16; r++) {
            cp_async16(sdst + (unsigned int)(r * 64),
                       in_feat + (size_t)js[r] * DD + t * 4);
        }
    };

    // ---------------- pipeline ----------------
    int j = blockIdx.x;
    if (j >= NCHUNK) return;
    stage(j, 0);
    cp_commit();
    int par = 0;

#pragma unroll 1
    while (j < NCHUNK) {
        int nxt = j + GRIDB;
        if (nxt < NCHUNK) {
            stage(nxt, par ^ 1);
            cp_commit();
            cp_wait1();
        } else {
            cp_wait0();
        }
        __syncwarp();

        // ---------------- compute chunk j from buffer par ----------------
        const int n = j * NPB + nb_;
        const float* frow = in_feat + (size_t)n * DD;
        const float* drow = dists   + (size_t)n * KK;
        const float* nodebuf = &snb[par][nb_ * NSTR];

        // k-invariant self contribution: sw[i] = b1[g] + self . W1[0:16][g]
        float sf[16];
        {
            const float4* p = reinterpret_cast<const float4*>(frow);
            float4 a = p[0], b = p[1], c = p[2], d = p[3];
            sf[0]  = a.x; sf[1]  = a.y; sf[2]  = a.z; sf[3]  = a.w;
            sf[4]  = b.x; sf[5]  = b.y; sf[6]  = b.z; sf[7]  = b.w;
            sf[8]  = c.x; sf[9]  = c.y; sf[10] = c.z; sf[11] = c.w;
            sf[12] = d.x; sf[13] = d.y; sf[14] = d.z; sf[15] = d.w;
        }
        float sw[9];
#pragma unroll
        for (int i = 0; i < 9; i++) {
            int g = t + 4 * i;
            const float4* wr = reinterpret_cast<const float4*>(&sW1T[g][0]);
            float4 w0 = wr[0], w1 = wr[1], w2 = wr[2], w3 = wr[3];
            float acc = sb1[g];
            acc += sf[0]  * w0.x + sf[1]  * w0.y + sf[2]  * w0.z + sf[3]  * w0.w;
            acc += sf[4]  * w1.x + sf[5]  * w1.y + sf[6]  * w1.z + sf[7]  * w1.w;
            acc += sf[8]  * w2.x + sf[9]  * w2.y + sf[10] * w2.z + sf[11] * w2.w;
            acc += sf[12] * w3.x + sf[13] * w3.y + sf[14] * w3.z + sf[15] * w3.w;
            sw[i] = acc;
        }

        float msg[16];
#pragma unroll
        for (int d = 0; d < 16; d++) msg[d] = 0.0f;

        // k-tile of 2: one weight-row load serves 2 edges; dual acc chains.
#pragma unroll 1
        for (int kk = 0; kk < KK; kk += 2) {
            float nb0[16], nb1[16];
            {
                const float4* r0 = reinterpret_cast<const float4*>(nodebuf + kk * 16);
                const float4* r1 = reinterpret_cast<const float4*>(nodebuf + (kk + 1) * 16);
                float4 a = r0[0], b = r0[1], c = r0[2], d = r0[3];
                nb0[0]  = a.x; nb0[1]  = a.y; nb0[2]  = a.z; nb0[3]  = a.w;
                nb0[4]  = b.x; nb0[5]  = b.y; nb0[6]  = b.z; nb0[7]  = b.w;
                nb0[8]  = c.x; nb0[9]  = c.y; nb0[10] = c.z; nb0[11] = c.w;
                nb0[12] = d.x; nb0[13] = d.y; nb0[14] = d.z; nb0[15] = d.w;
                a = r1[0]; b = r1[1]; c = r1[2]; d = r1[3];
                nb1[0]  = a.x; nb1[1]  = a.y; nb1[2]  = a.z; nb1[3]  = a.w;
                nb1[4]  = b.x; nb1[5]  = b.y; nb1[6]  = b.z; nb1[7]  = b.w;
                nb1[8]  = c.x; nb1[9]  = c.y; nb1[10] = c.z; nb1[11] = c.w;
                nb1[12] = d.x; nb1[13] = d.y; nb1[14] = d.z; nb1[15] = d.w;
            }
            float2 dk = *reinterpret_cast<const float2*>(drow + kk);

#pragma unroll
            for (int i = 0; i < 9; i++) {
                int g = t + 4 * i;
                const float4* wr = reinterpret_cast<const float4*>(&sW1T[g][16]);
                float4 w0 = wr[0], w1 = wr[1], w2 = wr[2], w3 = wr[3];
                float w1d = sW1T[g][32];
                float acc0 = fmaf(dk.x, w1d, sw[i]);
                float acc1 = fmaf(dk.y, w1d, sw[i]);
                acc0 += nb0[0]  * w0.x + nb0[1]  * w0.y + nb0[2]  * w0.z + nb0[3]  * w0.w;
                acc1 += nb1[0]  * w0.x + nb1[1]  * w0.y + nb1[2]  * w0.z + nb1[3]  * w0.w;
                acc0 += nb0[4]  * w1.x + nb0[5]  * w1.y + nb0[6]  * w1.z + nb0[7]  * w1.w;
                acc1 += nb1[4]  * w1.x + nb1[5]  * w1.y + nb1[6]  * w1.z + nb1[7]  * w1.w;
                acc0 += nb0[8]  * w2.x + nb0[9]  * w2.y + nb0[10] * w2.z + nb0[11] * w2.w;
                acc1 += nb1[8]  * w2.x + nb1[9]  * w2.y + nb1[10] * w2.z + nb1[11] * w2.w;
                acc0 += nb0[12] * w3.x + nb0[13] * w3.y + nb0[14] * w3.z + nb0[15] * w3.w;
                acc1 += nb1[12] * w3.x + nb1[13] * w3.y + nb1[14] * w3.z + nb1[15] * w3.w;
                float h0 = leaky(acc0);
                float h1 = leaky(acc1);
                const float4* ar = reinterpret_cast<const float4*>(&sW2p[g * 20]);
                float4 a0 = ar[0], a1 = ar[1], a2 = ar[2], a3 = ar[3];
                msg[0]  = fmaf(h0, a0.x, fmaf(h1, a0.x, msg[0]));
                msg[1]  = fmaf(h0, a0.y, fmaf(h1, a0.y, msg[1]));
                msg[2]  = fmaf(h0, a0.z, fmaf(h1, a0.z, msg[2]));
                msg[3]  = fmaf(h0, a0.w, fmaf(h1, a0.w, msg[3]));
                msg[4]  = fmaf(h0, a1.x, fmaf(h1, a1.x, msg[4]));
                msg[5]  = fmaf(h0, a1.y, fmaf(h1, a1.y, msg[5]));
                msg[6]  = fmaf(h0, a1.z, fmaf(h1, a1.z, msg[6]));
                msg[7]  = fmaf(h0, a1.w, fmaf(h1, a1.w, msg[7]));
                msg[8]  = fmaf(h0, a2.x, fmaf(h1, a2.x, msg[8]));
                msg[9]  = fmaf(h0, a2.y, fmaf(h1, a2.y, msg[9]));
                msg[10] = fmaf(h0, a2.z, fmaf(h1, a2.z, msg[10]));
                msg[11] = fmaf(h0, a2.w, fmaf(h1, a2.w, msg[11]));
                msg[12] = fmaf(h0, a3.x, fmaf(h1, a3.x, msg[12]));
                msg[13] = fmaf(h0, a3.y, fmaf(h1, a3.y, msg[13]));
                msg[14] = fmaf(h0, a3.z, fmaf(h1, a3.z, msg[14]));
                msg[15] = fmaf(h0, a3.w, fmaf(h1, a3.w, msg[15]));
            }
        }

        // Quad reduction + K*b2
#pragma unroll
        for (int d = 0; d < 16; d++) {
            msg[d] += __shfl_xor_sync(0xffffffffu, msg[d], 1);
            msg[d] += __shfl_xor_sync(0xffffffffu, msg[d], 2);
            msg[d] = fmaf((float)KK, sb2[d], msg[d]);
        }

        // GroupNorm (2 groups of 8) + leaky + residual
        float o[16];
#pragma unroll
        for (int grp = 0; grp < 2; grp++) {
            float mu = 0.0f, m2 = 0.0f;
#pragma unroll
            for (int c = 0; c < 8; c++) {
                float v = msg[grp * 8 + c];
                mu += v;
                m2 += v * v;
            }
            mu *= 0.125f;
            float var = m2 * 0.125f - mu * mu;
            float inv = rsqrtf(var + GN_EPS);
#pragma unroll
            for (int c = 0; c < 8; c++) {
                int d = grp * 8 + c;
                float xn = (msg[d] - mu) * inv;
                o[d] = sf[d] + leaky(xn * sgnw[d] + sgnb[d]);
            }
        }

        // Each lane stores its quarter of the output row.
        float4* orow = reinterpret_cast<float4*>(out_feat + (size_t)n * DD);
        if (t == 0)      orow[0] = make_float4(o[0],  o[1],  o[2],  o[3]);
        else if (t == 1) orow[1] = make_float4(o[4],  o[5],  o[6],  o[7]);
        else if (t == 2) orow[2] = make_float4(o[8],  o[9],  o[10], o[11]);
        else             orow[3] = make_float4(o[12], o[13], o[14], o[15]);

        par ^= 1;
        j = nxt;
    }
}

extern "C" void kernel_launch(void* const* d_in, const int* in_sizes, int n_in,
                              void* d_out, int out_size) {
    const float* y     = (const float*)d_in[0];
    const float* dists = (const float*)d_in[1];
    const float* W1    = (const float*)d_in[2];
    const float* b1    = (const float*)d_in[3];
    const float* W2    = (const float*)d_in[4];
    const float* b2    = (const float*)d_in[5];
    const float* gnw   = (const float*)d_in[6];
    const float* gnb   = (const float*)d_in[7];
    const void*  idx   = (const void*)d_in[8];
    float* out = (float*)d_out;

    float *buf0, *buf1;
    int* idx32;
    cudaGetSymbolAddress((void**)&buf0, g_buf0);
    cudaGetSymbolAddress((void**)&buf1, g_buf1);
    cudaGetSymbolAddress((void**)&idx32, g_idx32);

    detect_idx_kernel<<<1, 1>>>((const long long*)idx);
    convert_idx_kernel<<<(NN * KK + 255) / 256, 256>>>(idx);

    layer_kernel<<<GRIDB, 64>>>(y,    dists, idx32, W1,               b1,          W2,               b2,          gnw,          gnb,          buf0);
    layer_kernel<<<GRIDB, 64>>>(buf0, dists, idx32, W1 + 1 * FF * FF, b1 + 1 * FF, W2 + 1 * FF * DD, b2 + 1 * DD, gnw + 1 * DD, gnb + 1 * DD, buf1);
    layer_kernel<<<GRIDB, 64>>>(buf1, dists, idx32, W1 + 2 * FF * FF, b1 + 2 * FF, W2 + 2 * FF * DD, b2 + 2 * DD, gnw + 2 * DD, gnb + 2 * DD, out);
}

// round 9
// speedup vs baseline: 2.6533x; 1.0216x over previous
#include <cuda_runtime.h>
#include <cstdint>

#define NN 200000
#define DD 16
#define KK 16
#define FF 33
#define GN_EPS 1e-5f
#define SLOPE 0.2f

#define NPB 16                      // nodes per chunk (64 threads, 4 lanes/node)
#define NCHUNK (NN / NPB)           // 12500 exact
#define GRIDB 740                   // persistent blocks (5/SM * 148)
#define BUF_FLOATS (17 * NPB * 16)  // 16 nb rows + 1 dists row, 17408 B

typedef unsigned long long u64;

// Device globals (no allocation allowed)
__device__ float g_buf0[NN * DD];
__device__ float g_buf1[NN * DD];
__device__ int   g_idx32[NN * KK];
__device__ int   g_is64;

__global__ void detect_idx_kernel(const long long* __restrict__ p) {
    int ok = 1;
#pragma unroll 1
    for (int i = 0; i < 32; i++) {
        long long v = p[i];
        if (v < 0 || v >= NN) ok = 0;
    }
    g_is64 = ok;
}

__global__ __launch_bounds__(256) void convert_idx_kernel(const void* __restrict__ idxv) {
    int i = blockIdx.x * 256 + threadIdx.x;
    if (i >= NN * KK) return;
    long long v = g_is64 ? ((const long long*)idxv)[i]
                         : (long long)((const int*)idxv)[i];
    g_idx32[i] = (int)v;
}

__device__ __forceinline__ float leaky(float x) {
    return fmaf(SLOPE, fminf(x, 0.0f), fmaxf(x, 0.0f));
}

__device__ __forceinline__ u64 fma2(u64 a, u64 b, u64 c) {
    u64 d;
    asm("fma.rn.f32x2 %0, %1, %2, %3;" : "=l"(d) : "l"(a), "l"(b), "l"(c));
    return d;
}
__device__ __forceinline__ u64 add2(u64 a, u64 b) {
    u64 d;
    asm("add.rn.f32x2 %0, %1, %2;" : "=l"(d) : "l"(a), "l"(b));
    return d;
}
__device__ __forceinline__ u64 pack2(float lo, float hi) {
    u64 d;
    asm("mov.b64 %0, {%1, %2};" : "=l"(d) : "f"(lo), "f"(hi));
    return d;
}
__device__ __forceinline__ float2 unpack2(u64 v) {
    float2 r;
    asm("mov.b64 {%0, %1}, %2;" : "=f"(r.x), "=f"(r.y) : "l"(v));
    return r;
}

__device__ __forceinline__ void cp_async16(unsigned int smem_dst, const void* gsrc) {
    asm volatile("cp.async.cg.shared.global [%0], [%1], 16;\n" :: "r"(smem_dst), "l"(gsrc));
}
__device__ __forceinline__ void cp_commit() {
    asm volatile("cp.async.commit_group;\n" ::: "memory");
}
__device__ __forceinline__ void cp_wait1() {
    asm volatile("cp.async.wait_group 1;\n" ::: "memory");
}
__device__ __forceinline__ void cp_wait0() {
    asm volatile("cp.async.wait_group 0;\n" ::: "memory");
}

// Persistent kernel: 64 threads/block (16 nodes * 4 lanes/node), double-buffered
// cp.async staging; packed f32x2 (FFMA2) compute. Lane t owns g = t + 4i, i<9.
// Staging layout (per buffer): row-major [row 0..16][node 0..15][16 floats];
// row 16 holds the node's 16 dists. Warp reads of one row = 512B contiguous.
__global__ __launch_bounds__(64) void layer_kernel(
    const float* __restrict__ in_feat,   // [NN, DD]
    const float* __restrict__ dists,     // [NN, KK]
    const int*   __restrict__ idx32,     // [NN, KK]
    const float* __restrict__ W1,        // [FF, FF]
    const float* __restrict__ b1,        // [FF]
    const float* __restrict__ W2,        // [FF, DD]
    const float* __restrict__ b2,        // [DD]
    const float* __restrict__ gnw,       // [DD]
    const float* __restrict__ gnb,       // [DD]
    float* __restrict__ out_feat)        // [NN, DD]
{
    __shared__ float snb[2][BUF_FLOATS];   // 2 x 17408 B staging
    __shared__ float sW1T[36][36];         // W1 transposed [g][f], zero-padded (f 33..35 = 0)
    __shared__ float sW2[36][16];          // W2 [g][d], zero-padded rows
    __shared__ float sb1v[36];
    __shared__ float sb2[DD], sgnw[DD], sgnb[DD];

    for (int i = threadIdx.x; i < 36 * 36; i += 64) ((float*)sW1T)[i] = 0.0f;
    for (int i = threadIdx.x; i < 36 * 16; i += 64) ((float*)sW2)[i] = 0.0f;
    if (threadIdx.x < 36) sb1v[threadIdx.x] = 0.0f;
    __syncthreads();
    for (int i = threadIdx.x; i < FF * FF; i += 64) {
        int f = i / FF, g = i % FF;
        sW1T[g][f] = W1[i];
    }
    for (int i = threadIdx.x; i < FF * DD; i += 64) {
        sW2[i / DD][i % DD] = W2[i];
    }
    if (threadIdx.x < FF) sb1v[threadIdx.x] = b1[threadIdx.x];
    if (threadIdx.x < DD) {
        sb2[threadIdx.x]  = b2[threadIdx.x];
        sgnw[threadIdx.x] = gnw[threadIdx.x];
        sgnb[threadIdx.x] = gnb[threadIdx.x];
    }
    __syncthreads();

    const int tid = threadIdx.x;
    const int nb_ = tid >> 2;   // node slot (0..15)
    const int t   = tid & 3;    // lane within quad

    const unsigned int base0 =
        (unsigned int)__cvta_generic_to_shared(&snb[0][0]) + (unsigned int)(nb_ * 64 + t * 16);
    const unsigned int base1 =
        (unsigned int)__cvta_generic_to_shared(&snb[1][0]) + (unsigned int)(nb_ * 64 + t * 16);

    // Stage node (chunk*NPB + nb_): 16 neighbor rows + dists row; lane t copies quarter t.
    auto stage = [&](int chunk, int par) {
        int n = chunk * NPB + nb_;
        unsigned int dst = par ? base1 : base0;
        const int4* i4 = reinterpret_cast<const int4*>(idx32 + (size_t)n * KK);
        int4 ia = i4[0], ib = i4[1], ic = i4[2], id_ = i4[3];
        int js[16] = {ia.x, ia.y, ia.z, ia.w, ib.x, ib.y, ib.z, ib.w,
                      ic.x, ic.y, ic.z, ic.w, id_.x, id_.y, id_.z, id_.w};
#pragma unroll
        for (int r = 0; r < 16; r++) {
            cp_async16(dst + (unsigned int)(r * (NPB * 64)),
                       in_feat + (size_t)js[r] * DD + t * 4);
        }
        cp_async16(dst + (unsigned int)(16 * (NPB * 64)),
                   dists + (size_t)n * KK + t * 4);
    };

    int j = blockIdx.x;
    if (j >= NCHUNK) return;
    stage(j, 0);
    cp_commit();
    int par = 0;

#pragma unroll 1
    while (j < NCHUNK) {
        int nxt = j + GRIDB;
        if (nxt < NCHUNK) {
            stage(nxt, par ^ 1);
            cp_commit();
            cp_wait1();
        } else {
            cp_wait0();
        }
        __syncwarp();

        const int n = j * NPB + nb_;
        const float* buf = &snb[par][0];

        // Self features (L2/L1-hot LDG; quad lanes broadcast same row)
        float sf[16];
        {
            const float4* p = reinterpret_cast<const float4*>(in_feat + (size_t)n * DD);
            float4 a = p[0], b = p[1], c = p[2], d = p[3];
            sf[0]  = a.x; sf[1]  = a.y; sf[2]  = a.z; sf[3]  = a.w;
            sf[4]  = b.x; sf[5]  = b.y; sf[6]  = b.z; sf[7]  = b.w;
            sf[8]  = c.x; sf[9]  = c.y; sf[10] = c.z; sf[11] = c.w;
            sf[12] = d.x; sf[13] = d.y; sf[14] = d.z; sf[15] = d.w;
        }

        // k-invariant self term, packed: sw2[i] = {b1[g] + self.W1[0:16][g], 0}
        u64 sw2[9];
        {
            u64 sf2[8];
#pragma unroll
            for (int q = 0; q < 8; q++) sf2[q] = pack2(sf[2 * q], sf[2 * q + 1]);
#pragma unroll
            for (int i = 0; i < 9; i++) {
                int g = t + 4 * i;
                const ulonglong2* w = reinterpret_cast<const ulonglong2*>(&sW1T[g][0]);
                ulonglong2 wa = w[0], wb = w[1], wc = w[2], wd = w[3];
                u64 a = fma2(sf2[0], wa.x, pack2(sb1v[g], 0.0f));
                a = fma2(sf2[1], wa.y, a);
                a = fma2(sf2[2], wb.x, a);
                a = fma2(sf2[3], wb.y, a);
                a = fma2(sf2[4], wc.x, a);
                a = fma2(sf2[5], wc.y, a);
                a = fma2(sf2[6], wd.x, a);
                a = fma2(sf2[7], wd.y, a);
                float2 uv = unpack2(a);
                sw2[i] = pack2(uv.x + uv.y, 0.0f);
            }
        }

        u64 msg2[8];
#pragma unroll
        for (int q = 0; q < 8; q++) msg2[q] = 0ull;

        const int dbase = (16 * NPB + nb_) * 16;

#pragma unroll 1
        for (int k = 0; k < KK; k++) {
            const ulonglong2* nr =
                reinterpret_cast<const ulonglong2*>(buf + (k * NPB + nb_) * 16);
            ulonglong2 q0 = nr[0], q1 = nr[1], q2 = nr[2], q3 = nr[3];
            float dk = buf[dbase + k];
            u64 dk2 = pack2(dk, dk);
#pragma unroll
            for (int i = 0; i < 9; i++) {
                int g = t + 4 * i;
                const ulonglong2* w = reinterpret_cast<const ulonglong2*>(&sW1T[g][16]);
                ulonglong2 wa = w[0], wb = w[1], wc = w[2], wd = w[3];
                u64 wdk = *reinterpret_cast<const u64*>(&sW1T[g][32]);  // {w[32], 0}
                u64 a = fma2(q0.x, wa.x, sw2[i]);
                a = fma2(q0.y, wa.y, a);
                a = fma2(q1.x, wb.x, a);
                a = fma2(q1.y, wb.y, a);
                a = fma2(q2.x, wc.x, a);
                a = fma2(q2.y, wc.y, a);
                a = fma2(q3.x, wd.x, a);
                a = fma2(q3.y, wd.y, a);
                a = fma2(dk2, wdk, a);
                float2 uv = unpack2(a);
                float h = leaky(uv.x + uv.y);
                u64 h2 = pack2(h, h);
                const ulonglong2* w2r = reinterpret_cast<const ulonglong2*>(&sW2[g][0]);
                ulonglong2 m0 = w2r[0], m1 = w2r[1], m2 = w2r[2], m3 = w2r[3];
                msg2[0] = fma2(h2, m0.x, msg2[0]);
                msg2[1] = fma2(h2, m0.y, msg2[1]);
                msg2[2] = fma2(h2, m1.x, msg2[2]);
                msg2[3] = fma2(h2, m1.y, msg2[3]);
                msg2[4] = fma2(h2, m2.x, msg2[4]);
                msg2[5] = fma2(h2, m2.y, msg2[5]);
                msg2[6] = fma2(h2, m3.x, msg2[6]);
                msg2[7] = fma2(h2, m3.y, msg2[7]);
            }
        }

        // Quad reduction (packed), then unpack and add K*b2.
#pragma unroll
        for (int q = 0; q < 8; q++) {
            msg2[q] = add2(msg2[q], __shfl_xor_sync(0xffffffffu, msg2[q], 1));
            msg2[q] = add2(msg2[q], __shfl_xor_sync(0xffffffffu, msg2[q], 2));
        }
        float msg[16];
#pragma unroll
        for (int q = 0; q < 8; q++) {
            float2 uv = unpack2(msg2[q]);
            msg[2 * q]     = fmaf((float)KK, sb2[2 * q],     uv.x);
            msg[2 * q + 1] = fmaf((float)KK, sb2[2 * q + 1], uv.y);
        }

        // GroupNorm: lane computes only its own group's stats (grp = t>>1).
        int grp = t >> 1;
        float mu = 0.0f, m2s = 0.0f;
#pragma unroll
        for (int c = 0; c < 8; c++) {
            float v = msg[grp * 8 + c];
            mu += v;
            m2s += v * v;
        }
        mu *= 0.125f;
        float var = m2s * 0.125f - mu * mu;
        float inv = rsqrtf(var + GN_EPS);

        int d0 = 4 * t;
        float4 ov;
        ov.x = sf[d0 + 0] + leaky(fmaf((msg[d0 + 0] - mu) * inv, sgnw[d0 + 0], sgnb[d0 + 0]));
        ov.y = sf[d0 + 1] + leaky(fmaf((msg[d0 + 1] - mu) * inv, sgnw[d0 + 1], sgnb[d0 + 1]));
        ov.z = sf[d0 + 2] + leaky(fmaf((msg[d0 + 2] - mu) * inv, sgnw[d0 + 2], sgnb[d0 + 2]));
        ov.w = sf[d0 + 3] + leaky(fmaf((msg[d0 + 3] - mu) * inv, sgnw[d0 + 3], sgnb[d0 + 3]));
        reinterpret_cast<float4*>(out_feat + (size_t)n * DD)[t] = ov;

        par ^= 1;
        j = nxt;
    }
}

extern "C" void kernel_launch(void* const* d_in, const int* in_sizes, int n_in,
                              void* d_out, int out_size) {
    const float* y     = (const float*)d_in[0];
    const float* dists = (const float*)d_in[1];
    const float* W1    = (const float*)d_in[2];
    const float* b1    = (const float*)d_in[3];
    const float* W2    = (const float*)d_in[4];
    const float* b2    = (const float*)d_in[5];
    const float* gnw   = (const float*)d_in[6];
    const float* gnb   = (const float*)d_in[7];
    const void*  idx   = (const void*)d_in[8];
    float* out = (float*)d_out;

    float *buf0, *buf1;
    int* idx32;
    cudaGetSymbolAddress((void**)&buf0, g_buf0);
    cudaGetSymbolAddress((void**)&buf1, g_buf1);
    cudaGetSymbolAddress((void**)&idx32, g_idx32);

    detect_idx_kernel<<<1, 1>>>((const long long*)idx);
    convert_idx_kernel<<<(NN * KK + 255) / 256, 256>>>(idx);

    layer_kernel<<<GRIDB, 64>>>(y,    dists, idx32, W1,               b1,          W2,               b2,          gnw,          gnb,          buf0);
    layer_kernel<<<GRIDB, 64>>>(buf0, dists, idx32, W1 + 1 * FF * FF, b1 + 1 * FF, W2 + 1 * FF * DD, b2 + 1 * DD, gnw + 1 * DD, gnb + 1 * DD, buf1);
    layer_kernel<<<GRIDB, 64>>>(buf1, dists, idx32, W1 + 2 * FF * FF, b1 + 2 * FF, W2 + 2 * FF * DD, b2 + 2 * DD, gnw + 2 * DD, gnb + 2 * DD, out);
}

// round 10
// speedup vs baseline: 8.8365x; 3.3303x over previous
#include <cuda_runtime.h>
#include <cstdint>

#define NN 200000
#define DD 16
#define KK 16
#define FF 33
#define GN_EPS 1e-5f
#define SLOPE 0.2f

#define NPB 8                       // nodes per chunk (128 threads; warp = 2 nodes)
#define NCHUNK (NN / NPB)           // 25000 exact
#define GRIDB 888                   // persistent blocks (6/SM * 148)
#define RSTR 20                     // floats per staged row (80B, phase-conflict-free)
#define NODE_STR (KK * RSTR)        // 320 floats per node
#define BUF_FLOATS (NPB * NODE_STR) // 2560 floats per buffer

typedef unsigned long long u64;

// Device globals (no allocation allowed)
__device__ float g_buf0[NN * DD];
__device__ float g_buf1[NN * DD];
__device__ int   g_idx32[NN * KK];
__device__ int   g_is64;

__global__ void detect_idx_kernel(const long long* __restrict__ p) {
    int ok = 1;
#pragma unroll 1
    for (int i = 0; i < 32; i++) {
        long long v = p[i];
        if (v < 0 || v >= NN) ok = 0;
    }
    g_is64 = ok;
}

__global__ __launch_bounds__(256) void convert_idx_kernel(const void* __restrict__ idxv) {
    int i = blockIdx.x * 256 + threadIdx.x;
    if (i >= NN * KK) return;
    long long v = g_is64 ? ((const long long*)idxv)[i]
                         : (long long)((const int*)idxv)[i];
    g_idx32[i] = (int)v;
}

__device__ __forceinline__ float leaky(float x) {
    return fmaf(SLOPE, fminf(x, 0.0f), fmaxf(x, 0.0f));
}

__device__ __forceinline__ u64 fma2(u64 a, u64 b, u64 c) {
    u64 d;
    asm("fma.rn.f32x2 %0, %1, %2, %3;" : "=l"(d) : "l"(a), "l"(b), "l"(c));
    return d;
}
__device__ __forceinline__ u64 add2(u64 a, u64 b) {
    u64 d;
    asm("add.rn.f32x2 %0, %1, %2;" : "=l"(d) : "l"(a), "l"(b));
    return d;
}
__device__ __forceinline__ u64 pack2(float lo, float hi) {
    u64 d;
    asm("mov.b64 %0, {%1, %2};" : "=l"(d) : "f"(lo), "f"(hi));
    return d;
}
__device__ __forceinline__ float2 unpack2(u64 v) {
    float2 r;
    asm("mov.b64 {%0, %1}, %2;" : "=f"(r.x), "=f"(r.y) : "l"(v));
    return r;
}

__device__ __forceinline__ void cp_async16(unsigned int smem_dst, const void* gsrc) {
    asm volatile("cp.async.cg.shared.global [%0], [%1], 16;\n" :: "r"(smem_dst), "l"(gsrc));
}
__device__ __forceinline__ void cp_commit() {
    asm volatile("cp.async.commit_group;\n" ::: "memory");
}
__device__ __forceinline__ void cp_wait1() {
    asm volatile("cp.async.wait_group 1;\n" ::: "memory");
}
__device__ __forceinline__ void cp_wait0() {
    asm volatile("cp.async.wait_group 0;\n" ::: "memory");
}

// Persistent kernel, 128 threads/block = 4 warps = 8 nodes/chunk.
// Warp w owns nodes {2w, 2w+1}; lane = (half, k): lane's edge k of its node.
// g-outer loop: weight rows broadcast-read once per warp; neighbor row in regs.
__global__ __launch_bounds__(128, 6) void layer_kernel(
    const float* __restrict__ in_feat,   // [NN, DD]
    const float* __restrict__ dists,     // [NN, KK]
    const int*   __restrict__ idx32,     // [NN, KK]
    const float* __restrict__ W1,        // [FF, FF]
    const float* __restrict__ b1,        // [FF]
    const float* __restrict__ W2,        // [FF, DD]
    const float* __restrict__ b2,        // [DD]
    const float* __restrict__ gnw,       // [DD]
    const float* __restrict__ gnb,       // [DD]
    float* __restrict__ out_feat)        // [NN, DD]
{
    __shared__ float snb[2][BUF_FLOATS];   // 2 x 10240 B staging
    __shared__ float sW1T[FF][36];         // W1 transposed [g][f]
    __shared__ float sW2[FF][16];          // W2 [g][d]
    __shared__ float sSelf[NPB][33];       // per-chunk: b1[g] + self . W1[0:16][g]
    __shared__ float sb1v[FF];
    __shared__ float sb2[DD], sgnw[DD], sgnb[DD];

    for (int i = threadIdx.x; i < FF * FF; i += 128) {
        int f = i / FF, g = i % FF;
        sW1T[g][f] = W1[i];
    }
    for (int i = threadIdx.x; i < FF * DD; i += 128) {
        sW2[i / DD][i % DD] = W2[i];
    }
    if (threadIdx.x < FF) sb1v[threadIdx.x] = b1[threadIdx.x];
    if (threadIdx.x < DD) {
        sb2[threadIdx.x]  = b2[threadIdx.x];
        sgnw[threadIdx.x] = gnw[threadIdx.x];
        sgnb[threadIdx.x] = gnb[threadIdx.x];
    }
    __syncthreads();

    const int tid  = threadIdx.x;
    const int lane = tid & 31;
    const int wrp  = tid >> 5;           // 0..3
    const int half = lane >> 4;          // node half within warp
    const int k    = lane & 15;          // edge index
    const int ndl  = wrp * 2 + half;     // node slot within chunk (0..7)

    // Staging map: thread stages (node tid>>4, row tid&15) -> warp-local.
    const int s_nd = tid >> 4;
    const int s_r  = tid & 15;
    const unsigned int sb0 = (unsigned int)__cvta_generic_to_shared(&snb[0][0]);
    const unsigned int sb1a = (unsigned int)__cvta_generic_to_shared(&snb[1][0]);
    const unsigned int s_off = (unsigned int)((s_nd * NODE_STR + s_r * RSTR) * 4);

    auto stage = [&](int chunk, int par) {
        int n = chunk * NPB + s_nd;
        int jdx = idx32[(size_t)n * KK + s_r];
        const float* src = in_feat + (size_t)jdx * DD;
        unsigned int dst = (par ? sb1a : sb0) + s_off;
        cp_async16(dst,      src);
        cp_async16(dst + 16, src + 4);
        cp_async16(dst + 32, src + 8);
        cp_async16(dst + 48, src + 12);
    };

    int j = blockIdx.x;
    if (j >= NCHUNK) return;
    stage(j, 0);
    cp_commit();
    int par = 0;

#pragma unroll 1
    while (j < NCHUNK) {
        int nxt = j + GRIDB;
        if (nxt < NCHUNK) {
            stage(nxt, par ^ 1);
            cp_commit();
            cp_wait1();
        } else {
            cp_wait0();
        }
        __syncwarp();

        const int n = j * NPB + ndl;

        // ---- precompute sSelf[ndl][g] for g = k, k+16 (+32 for k==15), warp-local ----
        {
            u64 sf2[8];
            const float4* p = reinterpret_cast<const float4*>(in_feat + (size_t)n * DD);
            float4 a = p[0], b = p[1], c = p[2], d = p[3];
            sf2[0] = pack2(a.x, a.y); sf2[1] = pack2(a.z, a.w);
            sf2[2] = pack2(b.x, b.y); sf2[3] = pack2(b.z, b.w);
            sf2[4] = pack2(c.x, c.y); sf2[5] = pack2(c.z, c.w);
            sf2[6] = pack2(d.x, d.y); sf2[7] = pack2(d.z, d.w);
#pragma unroll
            for (int pass = 0; pass < 2; pass++) {
                int g = k + 16 * pass;
                const u64* w = reinterpret_cast<const u64*>(&sW1T[g][0]);
                u64 acc = fma2(sf2[0], w[0], pack2(sb1v[g], 0.0f));
                acc = fma2(sf2[1], w[1], acc);
                acc = fma2(sf2[2], w[2], acc);
                acc = fma2(sf2[3], w[3], acc);
                acc = fma2(sf2[4], w[4], acc);
                acc = fma2(sf2[5], w[5], acc);
                acc = fma2(sf2[6], w[6], acc);
                acc = fma2(sf2[7], w[7], acc);
                float2 uv = unpack2(acc);
                sSelf[ndl][g] = uv.x + uv.y;
            }
            if (k == 15) {
                const u64* w = reinterpret_cast<const u64*>(&sW1T[32][0]);
                u64 acc = fma2(sf2[0], w[0], pack2(sb1v[32], 0.0f));
                acc = fma2(sf2[1], w[1], acc);
                acc = fma2(sf2[2], w[2], acc);
                acc = fma2(sf2[3], w[3], acc);
                acc = fma2(sf2[4], w[4], acc);
                acc = fma2(sf2[5], w[5], acc);
                acc = fma2(sf2[6], w[6], acc);
                acc = fma2(sf2[7], w[7], acc);
                float2 uv = unpack2(acc);
                sSelf[ndl][32] = uv.x + uv.y;
            }
        }
        __syncwarp();

        // ---- load own edge's neighbor row (conflict-free LDS.128) + dist ----
        const float* nbrow = &snb[par][ndl * NODE_STR + k * RSTR];
        ulonglong2 q0 = reinterpret_cast<const ulonglong2*>(nbrow)[0];
        ulonglong2 q1 = *reinterpret_cast<const ulonglong2*>(nbrow + 4);
        ulonglong2 q2 = *reinterpret_cast<const ulonglong2*>(nbrow + 8);
        ulonglong2 q3 = *reinterpret_cast<const ulonglong2*>(nbrow + 12);
        const float dk = dists[(size_t)n * KK + k];

        u64 msg2[8];
#pragma unroll
        for (int q = 0; q < 8; q++) msg2[q] = 0ull;

        // ---- main loop over output features g; weights broadcast across warp ----
#pragma unroll 1
        for (int g = 0; g < FF; g++) {
            ulonglong2 wa = *reinterpret_cast<const ulonglong2*>(&sW1T[g][16]);
            ulonglong2 wb = *reinterpret_cast<const ulonglong2*>(&sW1T[g][20]);
            ulonglong2 wc = *reinterpret_cast<const ulonglong2*>(&sW1T[g][24]);
            ulonglong2 wd = *reinterpret_cast<const ulonglong2*>(&sW1T[g][28]);
            float swg = sSelf[ndl][g];
            float wdist = sW1T[g][32];
            u64 acc = pack2(fmaf(dk, wdist, swg), 0.0f);
            acc = fma2(q0.x, wa.x, acc);
            acc = fma2(q0.y, wa.y, acc);
            acc = fma2(q1.x, wb.x, acc);
            acc = fma2(q1.y, wb.y, acc);
            acc = fma2(q2.x, wc.x, acc);
            acc = fma2(q2.y, wc.y, acc);
            acc = fma2(q3.x, wd.x, acc);
            acc = fma2(q3.y, wd.y, acc);
            float2 uv = unpack2(acc);
            float h = leaky(uv.x + uv.y);
            u64 h2 = pack2(h, h);
            ulonglong2 m0 = *reinterpret_cast<const ulonglong2*>(&sW2[g][0]);
            ulonglong2 m1 = *reinterpret_cast<const ulonglong2*>(&sW2[g][4]);
            ulonglong2 m2 = *reinterpret_cast<const ulonglong2*>(&sW2[g][8]);
            ulonglong2 m3 = *reinterpret_cast<const ulonglong2*>(&sW2[g][12]);
            msg2[0] = fma2(h2, m0.x, msg2[0]);
            msg2[1] = fma2(h2, m0.y, msg2[1]);
            msg2[2] = fma2(h2, m1.x, msg2[2]);
            msg2[3] = fma2(h2, m1.y, msg2[3]);
            msg2[4] = fma2(h2, m2.x, msg2[4]);
            msg2[5] = fma2(h2, m2.y, msg2[5]);
            msg2[6] = fma2(h2, m3.x, msg2[6]);
            msg2[7] = fma2(h2, m3.y, msg2[7]);
        }

        // ---- reduce msg across the 16 edge-lanes of this node ----
#pragma unroll
        for (int q = 0; q < 8; q++) {
            msg2[q] = add2(msg2[q], __shfl_xor_sync(0xffffffffu, msg2[q], 1));
            msg2[q] = add2(msg2[q], __shfl_xor_sync(0xffffffffu, msg2[q], 2));
            msg2[q] = add2(msg2[q], __shfl_xor_sync(0xffffffffu, msg2[q], 4));
            msg2[q] = add2(msg2[q], __shfl_xor_sync(0xffffffffu, msg2[q], 8));
        }
        float msg[16];
#pragma unroll
        for (int q = 0; q < 8; q++) {
            float2 uv = unpack2(msg2[q]);
            msg[2 * q]     = fmaf((float)KK, sb2[2 * q],     uv.x);
            msg[2 * q + 1] = fmaf((float)KK, sb2[2 * q + 1], uv.y);
        }

        // ---- GroupNorm + leaky + residual; lanes k<4 store quarter k ----
        if (k < 4) {
            int grp = k >> 1;
            float mu = 0.0f, m2s = 0.0f;
#pragma unroll
            for (int c = 0; c < 8; c++) {
                float v = msg[grp * 8 + c];
                mu += v;
                m2s += v * v;
            }
            mu *= 0.125f;
            float var = m2s * 0.125f - mu * mu;
            float inv = rsqrtf(var + GN_EPS);

            float4 sq = reinterpret_cast<const float4*>(in_feat + (size_t)n * DD)[k];
            int d0 = 4 * k;
            float4 ov;
            ov.x = sq.x + leaky(fmaf((msg[d0 + 0] - mu) * inv, sgnw[d0 + 0], sgnb[d0 + 0]));
            ov.y = sq.y + leaky(fmaf((msg[d0 + 1] - mu) * inv, sgnw[d0 + 1], sgnb[d0 + 1]));
            ov.z = sq.z + leaky(fmaf((msg[d0 + 2] - mu) * inv, sgnw[d0 + 2], sgnb[d0 + 2]));
            ov.w = sq.w + leaky(fmaf((msg[d0 + 3] - mu) * inv, sgnw[d0 + 3], sgnb[d0 + 3]));
            reinterpret_cast<float4*>(out_feat + (size_t)n * DD)[k] = ov;
        }

        par ^= 1;
        j = nxt;
    }
}

extern "C" void kernel_launch(void* const* d_in, const int* in_sizes, int n_in,
                              void* d_out, int out_size) {
    const float* y     = (const float*)d_in[0];
    const float* dists = (const float*)d_in[1];
    const float* W1    = (const float*)d_in[2];
    const float* b1    = (const float*)d_in[3];
    const float* W2    = (const float*)d_in[4];
    const float* b2    = (const float*)d_in[5];
    const float* gnw   = (const float*)d_in[6];
    const float* gnb   = (const float*)d_in[7];
    const void*  idx   = (const void*)d_in[8];
    float* out = (float*)d_out;

    float *buf0, *buf1;
    int* idx32;
    cudaGetSymbolAddress((void**)&buf0, g_buf0);
    cudaGetSymbolAddress((void**)&buf1, g_buf1);
    cudaGetSymbolAddress((void**)&idx32, g_idx32);

    detect_idx_kernel<<<1, 1>>>((const long long*)idx);
    convert_idx_kernel<<<(NN * KK + 255) / 256, 256>>>(idx);

    layer_kernel<<<GRIDB, 128>>>(y,    dists, idx32, W1,               b1,          W2,               b2,          gnw,          gnb,          buf0);
    layer_kernel<<<GRIDB, 128>>>(buf0, dists, idx32, W1 + 1 * FF * FF, b1 + 1 * FF, W2 + 1 * FF * DD, b2 + 1 * DD, gnw + 1 * DD, gnb + 1 * DD, buf1);
    layer_kernel<<<GRIDB, 128>>>(buf1, dists, idx32, W1 + 2 * FF * FF, b1 + 2 * FF, W2 + 2 * FF * DD, b2 + 2 * DD, gnw + 2 * DD, gnb + 2 * DD, out);
}

// round 11
// speedup vs baseline: 11.2968x; 1.2784x over previous
#include <cuda_runtime.h>
#include <cstdint>

#define NN 200000
#define DD 16
#define KK 16
#define FF 33
#define GN_EPS 1e-5f
#define SLOPE 0.2f

#define NPB 16                      // nodes per chunk (4 warps x 4 nodes)
#define NCHUNK (NN / NPB)           // 12500 exact
#define GRIDB 592                   // persistent blocks (4/SM * 148)
#define NODE_FLOATS 256             // 16 rows x 16 floats, quarter-plane layout
#define BUF_FLOATS (NPB * NODE_FLOATS)

typedef unsigned long long u64;

// Device globals (no allocation allowed)
__device__ float g_buf0[NN * DD];
__device__ float g_buf1[NN * DD];
__device__ int   g_idx32[NN * KK];
__device__ int   g_is64;

__global__ void detect_idx_kernel(const long long* __restrict__ p) {
    int ok = 1;
#pragma unroll 1
    for (int i = 0; i < 32; i++) {
        long long v = p[i];
        if (v < 0 || v >= NN) ok = 0;
    }
    g_is64 = ok;
}

__global__ __launch_bounds__(256) void convert_idx_kernel(const void* __restrict__ idxv) {
    int i = blockIdx.x * 256 + threadIdx.x;
    if (i >= NN * KK) return;
    long long v = g_is64 ? ((const long long*)idxv)[i]
                         : (long long)((const int*)idxv)[i];
    g_idx32[i] = (int)v;
}

__device__ __forceinline__ float leaky(float x) {
    return fmaf(SLOPE, fminf(x, 0.0f), fmaxf(x, 0.0f));
}

__device__ __forceinline__ u64 fma2(u64 a, u64 b, u64 c) {
    u64 d;
    asm("fma.rn.f32x2 %0, %1, %2, %3;" : "=l"(d) : "l"(a), "l"(b), "l"(c));
    return d;
}
__device__ __forceinline__ u64 add2(u64 a, u64 b) {
    u64 d;
    asm("add.rn.f32x2 %0, %1, %2;" : "=l"(d) : "l"(a), "l"(b));
    return d;
}
__device__ __forceinline__ u64 pack2(float lo, float hi) {
    u64 d;
    asm("mov.b64 %0, {%1, %2};" : "=l"(d) : "f"(lo), "f"(hi));
    return d;
}
__device__ __forceinline__ float2 unpack2(u64 v) {
    float2 r;
    asm("mov.b64 {%0, %1}, %2;" : "=f"(r.x), "=f"(r.y) : "l"(v));
    return r;
}

__device__ __forceinline__ void cp_async16(unsigned int smem_dst, const void* gsrc) {
    asm volatile("cp.async.cg.shared.global [%0], [%1], 16;\n" :: "r"(smem_dst), "l"(gsrc));
}
__device__ __forceinline__ void cp_commit() {
    asm volatile("cp.async.commit_group;\n" ::: "memory");
}
__device__ __forceinline__ void cp_wait1() {
    asm volatile("cp.async.wait_group 1;\n" ::: "memory");
}
__device__ __forceinline__ void cp_wait0() {
    asm volatile("cp.async.wait_group 0;\n" ::: "memory");
}

// Persistent kernel, 128 threads = 4 warps; warp w owns nodes {4w..4w+3}.
// Lane = (half, k). Pair A = node 4w+half, pair B = node 4w+2+half; each lane
// holds edge k of BOTH nodes in registers -> weight broadcasts serve 4 nodes,
// and the two acc chains give 2x ILP.
// Staging layout per node (1024B): quarter q of row k at q*256 + k*16 bytes
// (conflict-free for cp.async writes and LDS.128 reads).
__global__ __launch_bounds__(128, 4) void layer_kernel(
    const float* __restrict__ in_feat,   // [NN, DD]
    const float* __restrict__ dists,     // [NN, KK]
    const int*   __restrict__ idx32,     // [NN, KK]
    const float* __restrict__ W1,        // [FF, FF]
    const float* __restrict__ b1,        // [FF]
    const float* __restrict__ W2,        // [FF, DD]
    const float* __restrict__ b2,        // [DD]
    const float* __restrict__ gnw,       // [DD]
    const float* __restrict__ gnb,       // [DD]
    float* __restrict__ out_feat)        // [NN, DD]
{
    __shared__ float snb[2][BUF_FLOATS];   // 2 x 16384 B staging
    __shared__ float sW1T[FF][36];         // W1 transposed [g][f]
    __shared__ float sW2[FF][16];          // W2 [g][d]
    __shared__ float sSelf[NPB][33];       // b1[g] + self . W1[0:16][g]
    __shared__ float sb1v[FF];
    __shared__ float sb2[DD], sgnw[DD], sgnb[DD];

    for (int i = threadIdx.x; i < FF * FF; i += 128) {
        int f = i / FF, g = i % FF;
        sW1T[g][f] = W1[i];
    }
    for (int i = threadIdx.x; i < FF * DD; i += 128) {
        sW2[i / DD][i % DD] = W2[i];
    }
    if (threadIdx.x < FF) sb1v[threadIdx.x] = b1[threadIdx.x];
    if (threadIdx.x < DD) {
        sb2[threadIdx.x]  = b2[threadIdx.x];
        sgnw[threadIdx.x] = gnw[threadIdx.x];
        sgnb[threadIdx.x] = gnb[threadIdx.x];
    }
    __syncthreads();

    const int tid  = threadIdx.x;
    const int lane = tid & 31;
    const int wrp  = tid >> 5;           // 0..3
    const int half = lane >> 4;          // 0/1
    const int k    = lane & 15;          // edge index
    const int slA  = wrp * 4 + half;     // node slot of pair A
    const int slB  = slA + 2;            // node slot of pair B

    // Staging map: thread stages rows {2*(tid&7), 2*(tid&7)+1} of node tid>>3.
    const int s_nd = tid >> 3;
    const int s_r0 = (tid & 7) * 2;
    const unsigned int sb0a = (unsigned int)__cvta_generic_to_shared(&snb[0][0]);
    const unsigned int sb1a = (unsigned int)__cvta_generic_to_shared(&snb[1][0]);

    auto stage = [&](int chunk, int par) {
        unsigned int nbase = (par ? sb1a : sb0a) + (unsigned int)(s_nd * 1024);
        int n = chunk * NPB + s_nd;
#pragma unroll
        for (int rr = 0; rr < 2; rr++) {
            int r = s_r0 + rr;
            int jdx = idx32[(size_t)n * KK + r];
            const float* src = in_feat + (size_t)jdx * DD;
            unsigned int dst = nbase + (unsigned int)(r * 16);
            cp_async16(dst,       src);
            cp_async16(dst + 256, src + 4);
            cp_async16(dst + 512, src + 8);
            cp_async16(dst + 768, src + 12);
        }
    };

    int j = blockIdx.x;
    if (j >= NCHUNK) return;
    stage(j, 0);
    cp_commit();
    int par = 0;

#pragma unroll 1
    while (j < NCHUNK) {
        int nxt = j + GRIDB;
        if (nxt < NCHUNK) {
            stage(nxt, par ^ 1);
            cp_commit();
            cp_wait1();
        } else {
            cp_wait0();
        }
        __syncwarp();

        const int nA = j * NPB + slA;
        const int nB = j * NPB + slB;

        // ---- precompute sSelf for both nodes (lane covers g=k, k+16, [32]) ----
        {
#pragma unroll
            for (int pn = 0; pn < 2; pn++) {
                int n = pn ? nB : nA;
                int sl = pn ? slB : slA;
                u64 sf2[8];
                const float4* p = reinterpret_cast<const float4*>(in_feat + (size_t)n * DD);
                float4 a = p[0], b = p[1], c = p[2], d = p[3];
                sf2[0] = pack2(a.x, a.y); sf2[1] = pack2(a.z, a.w);
                sf2[2] = pack2(b.x, b.y); sf2[3] = pack2(b.z, b.w);
                sf2[4] = pack2(c.x, c.y); sf2[5] = pack2(c.z, c.w);
                sf2[6] = pack2(d.x, d.y); sf2[7] = pack2(d.z, d.w);
#pragma unroll
                for (int pass = 0; pass < 2; pass++) {
                    int g = k + 16 * pass;
                    const u64* w = reinterpret_cast<const u64*>(&sW1T[g][0]);
                    u64 acc = fma2(sf2[0], w[0], pack2(sb1v[g], 0.0f));
                    acc = fma2(sf2[1], w[1], acc);
                    acc = fma2(sf2[2], w[2], acc);
                    acc = fma2(sf2[3], w[3], acc);
                    acc = fma2(sf2[4], w[4], acc);
                    acc = fma2(sf2[5], w[5], acc);
                    acc = fma2(sf2[6], w[6], acc);
                    acc = fma2(sf2[7], w[7], acc);
                    float2 uv = unpack2(acc);
                    sSelf[sl][g] = uv.x + uv.y;
                }
                if (k == 15) {
                    const u64* w = reinterpret_cast<const u64*>(&sW1T[32][0]);
                    u64 acc = fma2(sf2[0], w[0], pack2(sb1v[32], 0.0f));
                    acc = fma2(sf2[1], w[1], acc);
                    acc = fma2(sf2[2], w[2], acc);
                    acc = fma2(sf2[3], w[3], acc);
                    acc = fma2(sf2[4], w[4], acc);
                    acc = fma2(sf2[5], w[5], acc);
                    acc = fma2(sf2[6], w[6], acc);
                    acc = fma2(sf2[7], w[7], acc);
                    float2 uv = unpack2(acc);
                    sSelf[sl][32] = uv.x + uv.y;
                }
            }
        }
        __syncwarp();

        // ---- load both edge rows (quarter-plane layout, conflict-free) ----
        const float* bufp = &snb[par][0];
        const float* rowA = bufp + slA * NODE_FLOATS + k * 4;
        const float* rowB = bufp + slB * NODE_FLOATS + k * 4;
        ulonglong2 qA0 = *reinterpret_cast<const ulonglong2*>(rowA);
        ulonglong2 qA1 = *reinterpret_cast<const ulonglong2*>(rowA + 64);
        ulonglong2 qA2 = *reinterpret_cast<const ulonglong2*>(rowA + 128);
        ulonglong2 qA3 = *reinterpret_cast<const ulonglong2*>(rowA + 192);
        ulonglong2 qB0 = *reinterpret_cast<const ulonglong2*>(rowB);
        ulonglong2 qB1 = *reinterpret_cast<const ulonglong2*>(rowB + 64);
        ulonglong2 qB2 = *reinterpret_cast<const ulonglong2*>(rowB + 128);
        ulonglong2 qB3 = *reinterpret_cast<const ulonglong2*>(rowB + 192);
        const float dkA = dists[(size_t)nA * KK + k];
        const float dkB = dists[(size_t)nB * KK + k];

        u64 msgA[8], msgB[8];
#pragma unroll
        for (int q = 0; q < 8; q++) { msgA[q] = 0ull; msgB[q] = 0ull; }

        // ---- main g loop: weights broadcast once, serve 4 nodes, 2x ILP ----
#pragma unroll 1
        for (int g = 0; g < FF; g++) {
            ulonglong2 wa = *reinterpret_cast<const ulonglong2*>(&sW1T[g][16]);
            ulonglong2 wb = *reinterpret_cast<const ulonglong2*>(&sW1T[g][20]);
            ulonglong2 wc = *reinterpret_cast<const ulonglong2*>(&sW1T[g][24]);
            ulonglong2 wd = *reinterpret_cast<const ulonglong2*>(&sW1T[g][28]);
            float wdist = sW1T[g][32];
            u64 accA = pack2(fmaf(dkA, wdist, sSelf[slA][g]), 0.0f);
            u64 accB = pack2(fmaf(dkB, wdist, sSelf[slB][g]), 0.0f);
            accA = fma2(qA0.x, wa.x, accA);  accB = fma2(qB0.x, wa.x, accB);
            accA = fma2(qA0.y, wa.y, accA);  accB = fma2(qB0.y, wa.y, accB);
            accA = fma2(qA1.x, wb.x, accA);  accB = fma2(qB1.x, wb.x, accB);
            accA = fma2(qA1.y, wb.y, accA);  accB = fma2(qB1.y, wb.y, accB);
            accA = fma2(qA2.x, wc.x, accA);  accB = fma2(qB2.x, wc.x, accB);
            accA = fma2(qA2.y, wc.y, accA);  accB = fma2(qB2.y, wc.y, accB);
            accA = fma2(qA3.x, wd.x, accA);  accB = fma2(qB3.x, wd.x, accB);
            accA = fma2(qA3.y, wd.y, accA);  accB = fma2(qB3.y, wd.y, accB);
            float2 uA = unpack2(accA);
            float2 uB = unpack2(accB);
            float hA = leaky(uA.x + uA.y);
            float hB = leaky(uB.x + uB.y);
            u64 h2A = pack2(hA, hA);
            u64 h2B = pack2(hB, hB);
            ulonglong2 m0 = *reinterpret_cast<const ulonglong2*>(&sW2[g][0]);
            ulonglong2 m1 = *reinterpret_cast<const ulonglong2*>(&sW2[g][4]);
            ulonglong2 m2 = *reinterpret_cast<const ulonglong2*>(&sW2[g][8]);
            ulonglong2 m3 = *reinterpret_cast<const ulonglong2*>(&sW2[g][12]);
            msgA[0] = fma2(h2A, m0.x, msgA[0]);  msgB[0] = fma2(h2B, m0.x, msgB[0]);
            msgA[1] = fma2(h2A, m0.y, msgA[1]);  msgB[1] = fma2(h2B, m0.y, msgB[1]);
            msgA[2] = fma2(h2A, m1.x, msgA[2]);  msgB[2] = fma2(h2B, m1.x, msgB[2]);
            msgA[3] = fma2(h2A, m1.y, msgA[3]);  msgB[3] = fma2(h2B, m1.y, msgB[3]);
            msgA[4] = fma2(h2A, m2.x, msgA[4]);  msgB[4] = fma2(h2B, m2.x, msgB[4]);
            msgA[5] = fma2(h2A, m2.y, msgA[5]);  msgB[5] = fma2(h2B, m2.y, msgB[5]);
            msgA[6] = fma2(h2A, m3.x, msgA[6]);  msgB[6] = fma2(h2B, m3.x, msgB[6]);
            msgA[7] = fma2(h2A, m3.y, msgA[7]);  msgB[7] = fma2(h2B, m3.y, msgB[7]);
        }

        // ---- reduce over the 16 edge-lanes of each half ----
#pragma unroll
        for (int q = 0; q < 8; q++) {
            msgA[q] = add2(msgA[q], __shfl_xor_sync(0xffffffffu, msgA[q], 1));
            msgB[q] = add2(msgB[q], __shfl_xor_sync(0xffffffffu, msgB[q], 1));
            msgA[q] = add2(msgA[q], __shfl_xor_sync(0xffffffffu, msgA[q], 2));
            msgB[q] = add2(msgB[q], __shfl_xor_sync(0xffffffffu, msgB[q], 2));
            msgA[q] = add2(msgA[q], __shfl_xor_sync(0xffffffffu, msgA[q], 4));
            msgB[q] = add2(msgB[q], __shfl_xor_sync(0xffffffffu, msgB[q], 4));
            msgA[q] = add2(msgA[q], __shfl_xor_sync(0xffffffffu, msgA[q], 8));
            msgB[q] = add2(msgB[q], __shfl_xor_sync(0xffffffffu, msgB[q], 8));
        }

        // ---- GroupNorm + leaky + residual; lanes k<4 store quarter k ----
        if (k < 4) {
#pragma unroll
            for (int pn = 0; pn < 2; pn++) {
                const u64* m2p = pn ? msgB : msgA;
                int n = pn ? nB : nA;
                float msg[16];
#pragma unroll
                for (int q = 0; q < 8; q++) {
                    float2 uv = unpack2(m2p[q]);
                    msg[2 * q]     = fmaf((float)KK, sb2[2 * q],     uv.x);
                    msg[2 * q + 1] = fmaf((float)KK, sb2[2 * q + 1], uv.y);
                }
                int grp = k >> 1;
                float mu = 0.0f, m2s = 0.0f;
#pragma unroll
                for (int c = 0; c < 8; c++) {
                    float v = msg[grp * 8 + c];
                    mu += v;
                    m2s += v * v;
                }
                mu *= 0.125f;
                float var = m2s * 0.125f - mu * mu;
                float inv = rsqrtf(var + GN_EPS);

                float4 sq = reinterpret_cast<const float4*>(in_feat + (size_t)n * DD)[k];
                int d0 = 4 * k;
                float4 ov;
                ov.x = sq.x + leaky(fmaf((msg[d0 + 0] - mu) * inv, sgnw[d0 + 0], sgnb[d0 + 0]));
                ov.y = sq.y + leaky(fmaf((msg[d0 + 1] - mu) * inv, sgnw[d0 + 1], sgnb[d0 + 1]));
                ov.z = sq.z + leaky(fmaf((msg[d0 + 2] - mu) * inv, sgnw[d0 + 2], sgnb[d0 + 2]));
                ov.w = sq.w + leaky(fmaf((msg[d0 + 3] - mu) * inv, sgnw[d0 + 3], sgnb[d0 + 3]));
                reinterpret_cast<float4*>(out_feat + (size_t)n * DD)[k] = ov;
            }
        }

        par ^= 1;
        j = nxt;
    }
}

extern "C" void kernel_launch(void* const* d_in, const int* in_sizes, int n_in,
                              void* d_out, int out_size) {
    const float* y     = (const float*)d_in[0];
    const float* dists = (const float*)d_in[1];
    const float* W1    = (const float*)d_in[2];
    const float* b1    = (const float*)d_in[3];
    const float* W2    = (const float*)d_in[4];
    const float* b2    = (const float*)d_in[5];
    const float* gnw   = (const float*)d_in[6];
    const float* gnb   = (const float*)d_in[7];
    const void*  idx   = (const void*)d_in[8];
    float* out = (float*)d_out;

    float *buf0, *buf1;
    int* idx32;
    cudaGetSymbolAddress((void**)&buf0, g_buf0);
    cudaGetSymbolAddress((void**)&buf1, g_buf1);
    cudaGetSymbolAddress((void**)&idx32, g_idx32);

    detect_idx_kernel<<<1, 1>>>((const long long*)idx);
    convert_idx_kernel<<<(NN * KK + 255) / 256, 256>>>(idx);

    layer_kernel<<<GRIDB, 128>>>(y,    dists, idx32, W1,               b1,          W2,               b2,          gnw,          gnb,          buf0);
    layer_kernel<<<GRIDB, 128>>>(buf0, dists, idx32, W1 + 1 * FF * FF, b1 + 1 * FF, W2 + 1 * FF * DD, b2 + 1 * DD, gnw + 1 * DD, gnb + 1 * DD, buf1);
    layer_kernel<<<GRIDB, 128>>>(buf1, dists, idx32, W1 + 2 * FF * FF, b1 + 2 * FF, W2 + 2 * FF * DD, b2 + 2 * DD, gnw + 2 * DD, gnb + 2 * DD, out);
}

// round 12
// speedup vs baseline: 12.4862x; 1.1053x over previous
#include <cuda_runtime.h>
#include <cstdint>

#define NN 200000
#define DD 16
#define KK 16
#define FF 33
#define GN_EPS 1e-5f
#define SLOPE 0.2f

#define NPB 16                      // nodes per chunk (4 warps x 4 nodes)
#define NCHUNK (NN / NPB)           // 12500 exact
#define GRIDB 740                   // persistent blocks (5/SM * 148)
#define NODE_FLOATS 256             // 16 rows x 16 floats, quarter-plane layout
#define BUF_FLOATS (NPB * NODE_FLOATS)

typedef unsigned long long u64;

// Device globals (no allocation allowed)
__device__ float g_buf0[NN * DD];
__device__ float g_buf1[NN * DD];
__device__ int   g_idx32[NN * KK];
__device__ int   g_is64;

__global__ void detect_idx_kernel(const long long* __restrict__ p) {
    int ok = 1;
#pragma unroll 1
    for (int i = 0; i < 32; i++) {
        long long v = p[i];
        if (v < 0 || v >= NN) ok = 0;
    }
    g_is64 = ok;
}

__global__ __launch_bounds__(256) void convert_idx_kernel(const void* __restrict__ idxv) {
    int i = blockIdx.x * 256 + threadIdx.x;
    if (i >= NN * KK) return;
    long long v = g_is64 ? ((const long long*)idxv)[i]
                         : (long long)((const int*)idxv)[i];
    g_idx32[i] = (int)v;
}

__device__ __forceinline__ float leaky(float x) {
    return fmaf(SLOPE, fminf(x, 0.0f), fmaxf(x, 0.0f));
}

__device__ __forceinline__ u64 fma2(u64 a, u64 b, u64 c) {
    u64 d;
    asm("fma.rn.f32x2 %0, %1, %2, %3;" : "=l"(d) : "l"(a), "l"(b), "l"(c));
    return d;
}
__device__ __forceinline__ u64 pack2(float lo, float hi) {
    u64 d;
    asm("mov.b64 %0, {%1, %2};" : "=l"(d) : "f"(lo), "f"(hi));
    return d;
}
__device__ __forceinline__ float2 unpack2(u64 v) {
    float2 r;
    asm("mov.b64 {%0, %1}, %2;" : "=f"(r.x), "=f"(r.y) : "l"(v));
    return r;
}

__device__ __forceinline__ void cp_async16(unsigned int smem_dst, const void* gsrc) {
    asm volatile("cp.async.cg.shared.global [%0], [%1], 16;\n" :: "r"(smem_dst), "l"(gsrc));
}
__device__ __forceinline__ void cp_commit() {
    asm volatile("cp.async.commit_group;\n" ::: "memory");
}
__device__ __forceinline__ void cp_wait1() {
    asm volatile("cp.async.wait_group 1;\n" ::: "memory");
}
__device__ __forceinline__ void cp_wait0() {
    asm volatile("cp.async.wait_group 0;\n" ::: "memory");
}

// Persistent kernel, 128 threads = 4 warps; warp w owns nodes {4w..4w+3}.
// Lane = (half, k). Node A = 4w+half, node B = 4w+2+half; lane holds edge k of
// both in registers. Key algebra: sum_k(h_k @ W2) = (sum_k h_k) @ W2 -> per-g
// cross-lane h reduction into sHsum, single W2 matmul per node in the epilogue.
__global__ __launch_bounds__(128, 5) void layer_kernel(
    const float* __restrict__ in_feat,   // [NN, DD]
    const float* __restrict__ dists,     // [NN, KK]
    const int*   __restrict__ idx32,     // [NN, KK]
    const float* __restrict__ W1,        // [FF, FF]
    const float* __restrict__ b1,        // [FF]
    const float* __restrict__ W2,        // [FF, DD]
    const float* __restrict__ b2,        // [DD]
    const float* __restrict__ gnw,       // [DD]
    const float* __restrict__ gnb,       // [DD]
    float* __restrict__ out_feat)        // [NN, DD]
{
    __shared__ float snb[2][BUF_FLOATS];   // 2 x 16384 B staging
    __shared__ float sW1T[FF][36];         // W1 transposed [g][f]
    __shared__ float sW2T[16][36];         // W2 transposed [d][g] (g padded to 36)
    __shared__ float sSelf[NPB][33];       // b1[g] + self . W1[0:16][g]
    __shared__ float sHsum[NPB][36];       // per-node sum_k h[k][g]
    __shared__ float sb1v[FF];
    __shared__ float sb2[DD], sgnw[DD], sgnb[DD];

    for (int i = threadIdx.x; i < FF * FF; i += 128) {
        int f = i / FF, g = i % FF;
        sW1T[g][f] = W1[i];
    }
    for (int i = threadIdx.x; i < FF * DD; i += 128) {
        sW2T[i % DD][i / DD] = W2[i];
    }
    if (threadIdx.x < FF) sb1v[threadIdx.x] = b1[threadIdx.x];
    if (threadIdx.x < DD) {
        sb2[threadIdx.x]  = b2[threadIdx.x];
        sgnw[threadIdx.x] = gnw[threadIdx.x];
        sgnb[threadIdx.x] = gnb[threadIdx.x];
    }
    __syncthreads();

    const int tid  = threadIdx.x;
    const int lane = tid & 31;
    const int wrp  = tid >> 5;           // 0..3
    const int half = lane >> 4;          // 0/1
    const int k    = lane & 15;          // edge index
    const int slA  = wrp * 4 + half;     // node slot of chain A
    const int slB  = slA + 2;            // node slot of chain B
    const bool k0  = (k == 0);

    // Staging map: thread stages rows {2*(tid&7), 2*(tid&7)+1} of node tid>>3 (warp-local).
    const int s_nd = tid >> 3;
    const int s_r0 = (tid & 7) * 2;
    const unsigned int sb0a = (unsigned int)__cvta_generic_to_shared(&snb[0][0]);
    const unsigned int sb1a = (unsigned int)__cvta_generic_to_shared(&snb[1][0]);

    auto stage = [&](int chunk, int par) {
        unsigned int nbase = (par ? sb1a : sb0a) + (unsigned int)(s_nd * 1024);
        int n = chunk * NPB + s_nd;
#pragma unroll
        for (int rr = 0; rr < 2; rr++) {
            int r = s_r0 + rr;
            int jdx = idx32[(size_t)n * KK + r];
            const float* src = in_feat + (size_t)jdx * DD;
            unsigned int dst = nbase + (unsigned int)(r * 16);
            cp_async16(dst,       src);
            cp_async16(dst + 256, src + 4);
            cp_async16(dst + 512, src + 8);
            cp_async16(dst + 768, src + 12);
        }
    };

    int j = blockIdx.x;
    if (j >= NCHUNK) return;
    stage(j, 0);
    cp_commit();
    int par = 0;

#pragma unroll 1
    while (j < NCHUNK) {
        int nxt = j + GRIDB;
        if (nxt < NCHUNK) {
            stage(nxt, par ^ 1);
            cp_commit();
            cp_wait1();
        } else {
            cp_wait0();
        }
        __syncwarp();

        const int nA = j * NPB + slA;
        const int nB = j * NPB + slB;

        // ---- precompute sSelf for both nodes (lane covers g=k, k+16, [32]) ----
#pragma unroll
        for (int pn = 0; pn < 2; pn++) {
            int n = pn ? nB : nA;
            int sl = pn ? slB : slA;
            u64 sf2[8];
            const float4* p = reinterpret_cast<const float4*>(in_feat + (size_t)n * DD);
            float4 a = p[0], b = p[1], c = p[2], d = p[3];
            sf2[0] = pack2(a.x, a.y); sf2[1] = pack2(a.z, a.w);
            sf2[2] = pack2(b.x, b.y); sf2[3] = pack2(b.z, b.w);
            sf2[4] = pack2(c.x, c.y); sf2[5] = pack2(c.z, c.w);
            sf2[6] = pack2(d.x, d.y); sf2[7] = pack2(d.z, d.w);
#pragma unroll
            for (int pass = 0; pass < 2; pass++) {
                int g = k + 16 * pass;
                const u64* w = reinterpret_cast<const u64*>(&sW1T[g][0]);
                u64 acc = fma2(sf2[0], w[0], pack2(sb1v[g], 0.0f));
                acc = fma2(sf2[1], w[1], acc);
                acc = fma2(sf2[2], w[2], acc);
                acc = fma2(sf2[3], w[3], acc);
                acc = fma2(sf2[4], w[4], acc);
                acc = fma2(sf2[5], w[5], acc);
                acc = fma2(sf2[6], w[6], acc);
                acc = fma2(sf2[7], w[7], acc);
                float2 uv = unpack2(acc);
                sSelf[sl][g] = uv.x + uv.y;
            }
            if (k == 15) {
                const u64* w = reinterpret_cast<const u64*>(&sW1T[32][0]);
                u64 acc = fma2(sf2[0], w[0], pack2(sb1v[32], 0.0f));
                acc = fma2(sf2[1], w[1], acc);
                acc = fma2(sf2[2], w[2], acc);
                acc = fma2(sf2[3], w[3], acc);
                acc = fma2(sf2[4], w[4], acc);
                acc = fma2(sf2[5], w[5], acc);
                acc = fma2(sf2[6], w[6], acc);
                acc = fma2(sf2[7], w[7], acc);
                float2 uv = unpack2(acc);
                sSelf[sl][32] = uv.x + uv.y;
            }
        }
        __syncwarp();

        // ---- load both edge rows (quarter-plane layout, conflict-free) ----
        const float* bufp = &snb[par][0];
        const float* rowA = bufp + slA * NODE_FLOATS + k * 4;
        const float* rowB = bufp + slB * NODE_FLOATS + k * 4;
        ulonglong2 qA0 = *reinterpret_cast<const ulonglong2*>(rowA);
        ulonglong2 qA1 = *reinterpret_cast<const ulonglong2*>(rowA + 64);
        ulonglong2 qA2 = *reinterpret_cast<const ulonglong2*>(rowA + 128);
        ulonglong2 qA3 = *reinterpret_cast<const ulonglong2*>(rowA + 192);
        ulonglong2 qB0 = *reinterpret_cast<const ulonglong2*>(rowB);
        ulonglong2 qB1 = *reinterpret_cast<const ulonglong2*>(rowB + 64);
        ulonglong2 qB2 = *reinterpret_cast<const ulonglong2*>(rowB + 128);
        ulonglong2 qB3 = *reinterpret_cast<const ulonglong2*>(rowB + 192);
        const float dkA = dists[(size_t)nA * KK + k];
        const float dkB = dists[(size_t)nB * KK + k];

        // ---- main g loop: h chains + cross-lane h reduction into sHsum ----
#pragma unroll 1
        for (int g = 0; g < FF; g++) {
            ulonglong2 wa = *reinterpret_cast<const ulonglong2*>(&sW1T[g][16]);
            ulonglong2 wb = *reinterpret_cast<const ulonglong2*>(&sW1T[g][20]);
            ulonglong2 wc = *reinterpret_cast<const ulonglong2*>(&sW1T[g][24]);
            ulonglong2 wd = *reinterpret_cast<const ulonglong2*>(&sW1T[g][28]);
            float wdist = sW1T[g][32];
            float baseA = fmaf(dkA, wdist, sSelf[slA][g]);
            float baseB = fmaf(dkB, wdist, sSelf[slB][g]);
            u64 accA = fma2(qA0.x, wa.x, 0ull);
            u64 accB = fma2(qB0.x, wa.x, 0ull);
            accA = fma2(qA0.y, wa.y, accA);  accB = fma2(qB0.y, wa.y, accB);
            accA = fma2(qA1.x, wb.x, accA);  accB = fma2(qB1.x, wb.x, accB);
            accA = fma2(qA1.y, wb.y, accA);  accB = fma2(qB1.y, wb.y, accB);
            accA = fma2(qA2.x, wc.x, accA);  accB = fma2(qB2.x, wc.x, accB);
            accA = fma2(qA2.y, wc.y, accA);  accB = fma2(qB2.y, wc.y, accB);
            accA = fma2(qA3.x, wd.x, accA);  accB = fma2(qB3.x, wd.x, accB);
            accA = fma2(qA3.y, wd.y, accA);  accB = fma2(qB3.y, wd.y, accB);
            float2 uA = unpack2(accA);
            float2 uB = unpack2(accB);
            float hA = leaky(uA.x + uA.y + baseA);
            float hB = leaky(uB.x + uB.y + baseB);
            // reduce over the 16 edge-lanes of each half
            hA += __shfl_xor_sync(0xffffffffu, hA, 1);
            hB += __shfl_xor_sync(0xffffffffu, hB, 1);
            hA += __shfl_xor_sync(0xffffffffu, hA, 2);
            hB += __shfl_xor_sync(0xffffffffu, hB, 2);
            hA += __shfl_xor_sync(0xffffffffu, hA, 4);
            hB += __shfl_xor_sync(0xffffffffu, hB, 4);
            hA += __shfl_xor_sync(0xffffffffu, hA, 8);
            hB += __shfl_xor_sync(0xffffffffu, hB, 8);
            if (k0) {
                sHsum[slA][g] = hA;
                sHsum[slB][g] = hB;
            }
        }
        __syncwarp();

        // ---- epilogue: msg = 16*b2 + hsum @ W2 (lane owns channel d=k) ----
        {
            const float* w2r = &sW2T[k][0];
            const float* hsA = &sHsum[slA][0];
            const float* hsB = &sHsum[slB][0];
            float mA = 16.0f * sb2[k];
            float mB = mA;
#pragma unroll
            for (int jj = 0; jj < 8; jj++) {
                float4 w  = *reinterpret_cast<const float4*>(w2r + 4 * jj);
                float4 ha = *reinterpret_cast<const float4*>(hsA + 4 * jj);
                float4 hb = *reinterpret_cast<const float4*>(hsB + 4 * jj);
                mA += ha.x * w.x + ha.y * w.y + ha.z * w.z + ha.w * w.w;
                mB += hb.x * w.x + hb.y * w.y + hb.z * w.z + hb.w * w.w;
            }
            mA = fmaf(hsA[32], w2r[32], mA);
            mB = fmaf(hsB[32], w2r[32], mB);

            // GroupNorm stats over the 8-lane channel group (d 0-7 | 8-15)
            float muA = mA, m2A = mA * mA;
            float muB = mB, m2B = mB * mB;
#pragma unroll
            for (int off = 1; off < 8; off <<= 1) {
                muA += __shfl_xor_sync(0xffffffffu, muA, off);
                m2A += __shfl_xor_sync(0xffffffffu, m2A, off);
                muB += __shfl_xor_sync(0xffffffffu, muB, off);
                m2B += __shfl_xor_sync(0xffffffffu, m2B, off);
            }
            muA *= 0.125f; muB *= 0.125f;
            float invA = rsqrtf(fmaf(-muA, muA, m2A * 0.125f) + GN_EPS);
            float invB = rsqrtf(fmaf(-muB, muB, m2B * 0.125f) + GN_EPS);
            float oA = in_feat[(size_t)nA * DD + k] +
                       leaky(fmaf((mA - muA) * invA, sgnw[k], sgnb[k]));
            float oB = in_feat[(size_t)nB * DD + k] +
                       leaky(fmaf((mB - muB) * invB, sgnw[k], sgnb[k]));
            out_feat[(size_t)nA * DD + k] = oA;
            out_feat[(size_t)nB * DD + k] = oB;
        }

        par ^= 1;
        j = nxt;
    }
}

extern "C" void kernel_launch(void* const* d_in, const int* in_sizes, int n_in,
                              void* d_out, int out_size) {
    const float* y     = (const float*)d_in[0];
    const float* dists = (const float*)d_in[1];
    const float* W1    = (const float*)d_in[2];
    const float* b1    = (const float*)d_in[3];
    const float* W2    = (const float*)d_in[4];
    const float* b2    = (const float*)d_in[5];
    const float* gnw   = (const float*)d_in[6];
    const float* gnb   = (const float*)d_in[7];
    const void*  idx   = (const void*)d_in[8];
    float* out = (float*)d_out;

    float *buf0, *buf1;
    int* idx32;
    cudaGetSymbolAddress((void**)&buf0, g_buf0);
    cudaGetSymbolAddress((void**)&buf1, g_buf1);
    cudaGetSymbolAddress((void**)&idx32, g_idx32);

    detect_idx_kernel<<<1, 1>>>((const long long*)idx);
    convert_idx_kernel<<<(NN * KK + 255) / 256, 256>>>(idx);

    layer_kernel<<<GRIDB, 128>>>(y,    dists, idx32, W1,               b1,          W2,               b2,          gnw,          gnb,          buf0);
    layer_kernel<<<GRIDB, 128>>>(buf0, dists, idx32, W1 + 1 * FF * FF, b1 + 1 * FF, W2 + 1 * FF * DD, b2 + 1 * DD, gnw + 1 * DD, gnb + 1 * DD, buf1);
    layer_kernel<<<GRIDB, 128>>>(buf1, dists, idx32, W1 + 2 * FF * FF, b1 + 2 * FF, W2 + 2 * FF * DD, b2 + 2 * DD, gnw + 2 * DD, gnb + 2 * DD, out);
}

// round 13
// speedup vs baseline: 15.0772x; 1.2075x over previous
#include <cuda_runtime.h>
#include <cstdint>

#define NN 200000
#define DD 16
#define KK 16
#define FF 33
#define GN_EPS 1e-5f
#define SLOPE 0.2f

#define NPB 16                      // nodes per chunk (4 warps x 4 nodes)
#define NCHUNK (NN / NPB)           // 12500 exact
#define GRIDB 740                   // persistent blocks (5/SM * 148)
#define NODE_FLOATS 256             // 16 rows x 16 floats, quarter-plane layout
#define BUF_FLOATS (NPB * NODE_FLOATS)

typedef unsigned long long u64;

// Device globals (no allocation allowed)
__device__ float g_buf0[NN * DD];
__device__ float g_buf1[NN * DD];
__device__ int   g_idx32[NN * KK];
__device__ int   g_is64;

__global__ void detect_idx_kernel(const long long* __restrict__ p) {
    int ok = 1;
#pragma unroll 1
    for (int i = 0; i < 32; i++) {
        long long v = p[i];
        if (v < 0 || v >= NN) ok = 0;
    }
    g_is64 = ok;
}

__global__ __launch_bounds__(256) void convert_idx_kernel(const void* __restrict__ idxv) {
    int i = blockIdx.x * 256 + threadIdx.x;
    if (i >= NN * KK) return;
    long long v = g_is64 ? ((const long long*)idxv)[i]
                         : (long long)((const int*)idxv)[i];
    g_idx32[i] = (int)v;
}

__device__ __forceinline__ float leaky(float x) {
    return fmaf(SLOPE, fminf(x, 0.0f), fmaxf(x, 0.0f));
}

__device__ __forceinline__ u64 fma2(u64 a, u64 b, u64 c) {
    u64 d;
    asm("fma.rn.f32x2 %0, %1, %2, %3;" : "=l"(d) : "l"(a), "l"(b), "l"(c));
    return d;
}
__device__ __forceinline__ u64 pack2(float lo, float hi) {
    u64 d;
    asm("mov.b64 %0, {%1, %2};" : "=l"(d) : "f"(lo), "f"(hi));
    return d;
}
__device__ __forceinline__ float2 unpack2(u64 v) {
    float2 r;
    asm("mov.b64 {%0, %1}, %2;" : "=f"(r.x), "=f"(r.y) : "l"(v));
    return r;
}

__device__ __forceinline__ void cp_async16(unsigned int smem_dst, const void* gsrc) {
    asm volatile("cp.async.cg.shared.global [%0], [%1], 16;\n" :: "r"(smem_dst), "l"(gsrc));
}
__device__ __forceinline__ void cp_commit() {
    asm volatile("cp.async.commit_group;\n" ::: "memory");
}
__device__ __forceinline__ void cp_wait1() {
    asm volatile("cp.async.wait_group 1;\n" ::: "memory");
}
__device__ __forceinline__ void cp_wait0() {
    asm volatile("cp.async.wait_group 0;\n" ::: "memory");
}

// Persistent kernel, 128 threads = 4 warps; warp w owns nodes {4w..4w+3}.
// g-per-lane: lane g keeps W1T[g][16:33] in registers; per (node, k) the
// neighbor row is broadcast from staging, each lane does its private dot and
// accumulates hsum[g] in a register (k-reduction is free: no shfl, no weight
// LDS in the main loop). g=32 handled by an edge-parallel side pass.
// Epilogue: msg = 16*b2 + hsum @ W2 with lane owning channel d, then GN.
__global__ __launch_bounds__(128, 5) void layer_kernel(
    const float* __restrict__ in_feat,   // [NN, DD]
    const float* __restrict__ dists,     // [NN, KK]
    const int*   __restrict__ idx32,     // [NN, KK]
    const float* __restrict__ W1,        // [FF, FF]
    const float* __restrict__ b1,        // [FF]
    const float* __restrict__ W2,        // [FF, DD]
    const float* __restrict__ b2,        // [DD]
    const float* __restrict__ gnw,       // [DD]
    const float* __restrict__ gnb,       // [DD]
    float* __restrict__ out_feat)        // [NN, DD]
{
    __shared__ float snb[2][BUF_FLOATS];   // 2 x 16384 B staging (quarter-plane)
    __shared__ float sW1T[FF][36];         // W1 transposed [g][f]
    __shared__ float sW2T[16][36];         // W2 transposed [d][g]
    __shared__ float sSelf[NPB][33];       // b1[g] + self . W1[0:16][g]
    __shared__ float sHsum[NPB][36];       // per-node sum_k h[k][g]
    __shared__ float sb1v[FF];
    __shared__ float sb2[DD], sgnw[DD], sgnb[DD];

    for (int i = threadIdx.x; i < FF * FF; i += 128) {
        int f = i / FF, g = i % FF;
        sW1T[g][f] = W1[i];
    }
    for (int i = threadIdx.x; i < FF * DD; i += 128) {
        sW2T[i % DD][i / DD] = W2[i];
    }
    if (threadIdx.x < FF) sb1v[threadIdx.x] = b1[threadIdx.x];
    if (threadIdx.x < DD) {
        sb2[threadIdx.x]  = b2[threadIdx.x];
        sgnw[threadIdx.x] = gnw[threadIdx.x];
        sgnb[threadIdx.x] = gnb[threadIdx.x];
    }
    __syncthreads();

    const int tid  = threadIdx.x;
    const int lane = tid & 31;
    const int wrp  = tid >> 5;           // 0..3
    const int half = lane >> 4;          // 0/1
    const int k    = lane & 15;          // edge / channel index
    const int slA  = wrp * 4 + half;     // epilogue node of this half
    const int slB  = slA + 2;

    // Register-resident W1 row for g = lane (16B-aligned: 36*4*lane + 64)
    const ulonglong2 wA = *reinterpret_cast<const ulonglong2*>(&sW1T[lane][16]);
    const ulonglong2 wB = *reinterpret_cast<const ulonglong2*>(&sW1T[lane][20]);
    const ulonglong2 wC = *reinterpret_cast<const ulonglong2*>(&sW1T[lane][24]);
    const ulonglong2 wD = *reinterpret_cast<const ulonglong2*>(&sW1T[lane][28]);
    const float wdist = sW1T[lane][32];

    // Staging map (warp-local): thread stages rows {2*(tid&7), 2*(tid&7)+1} of node tid>>3.
    const int s_nd = tid >> 3;
    const int s_r0 = (tid & 7) * 2;
    const unsigned int sb0a = (unsigned int)__cvta_generic_to_shared(&snb[0][0]);
    const unsigned int sb1a = (unsigned int)__cvta_generic_to_shared(&snb[1][0]);

    auto stage = [&](int chunk, int par) {
        unsigned int nbase = (par ? sb1a : sb0a) + (unsigned int)(s_nd * 1024);
        int n = chunk * NPB + s_nd;
#pragma unroll
        for (int rr = 0; rr < 2; rr++) {
            int r = s_r0 + rr;
            int jdx = idx32[(size_t)n * KK + r];
            const float* src = in_feat + (size_t)jdx * DD;
            unsigned int dst = nbase + (unsigned int)(r * 16);
            cp_async16(dst,       src);
            cp_async16(dst + 256, src + 4);
            cp_async16(dst + 512, src + 8);
            cp_async16(dst + 768, src + 12);
        }
    };

    int j = blockIdx.x;
    if (j >= NCHUNK) return;
    stage(j, 0);
    cp_commit();
    int par = 0;

#pragma unroll 1
    while (j < NCHUNK) {
        int nxt = j + GRIDB;
        if (nxt < NCHUNK) {
            stage(nxt, par ^ 1);
            cp_commit();
            cp_wait1();
        } else {
            cp_wait0();
        }
        __syncwarp();

        // Prefetch dists of node 0 (broadcast, L2-hot)
        float4 dq0, dq1, dq2, dq3;
        {
            const float4* dp = reinterpret_cast<const float4*>(
                dists + (size_t)(j * NPB + wrp * 4) * KK);
            dq0 = dp[0]; dq1 = dp[1]; dq2 = dp[2]; dq3 = dp[3];
        }

        // ---- sSelf precompute (edge-parallel; lane covers g=k, k+16, [32]) ----
        const int nA = j * NPB + slA;
        const int nB = j * NPB + slB;
#pragma unroll
        for (int pn = 0; pn < 2; pn++) {
            int n = pn ? nB : nA;
            int sl = pn ? slB : slA;
            u64 sf2[8];
            const float4* p = reinterpret_cast<const float4*>(in_feat + (size_t)n * DD);
            float4 a = p[0], b = p[1], c = p[2], d = p[3];
            sf2[0] = pack2(a.x, a.y); sf2[1] = pack2(a.z, a.w);
            sf2[2] = pack2(b.x, b.y); sf2[3] = pack2(b.z, b.w);
            sf2[4] = pack2(c.x, c.y); sf2[5] = pack2(c.z, c.w);
            sf2[6] = pack2(d.x, d.y); sf2[7] = pack2(d.z, d.w);
#pragma unroll
            for (int pass = 0; pass < 2; pass++) {
                int g = k + 16 * pass;
                const u64* w = reinterpret_cast<const u64*>(&sW1T[g][0]);
                u64 acc = fma2(sf2[0], w[0], pack2(sb1v[g], 0.0f));
                acc = fma2(sf2[1], w[1], acc);
                acc = fma2(sf2[2], w[2], acc);
                acc = fma2(sf2[3], w[3], acc);
                acc = fma2(sf2[4], w[4], acc);
                acc = fma2(sf2[5], w[5], acc);
                acc = fma2(sf2[6], w[6], acc);
                acc = fma2(sf2[7], w[7], acc);
                float2 uv = unpack2(acc);
                sSelf[sl][g] = uv.x + uv.y;
            }
            if (k == 15) {
                const u64* w = reinterpret_cast<const u64*>(&sW1T[32][0]);
                u64 acc = fma2(sf2[0], w[0], pack2(sb1v[32], 0.0f));
                acc = fma2(sf2[1], w[1], acc);
                acc = fma2(sf2[2], w[2], acc);
                acc = fma2(sf2[3], w[3], acc);
                acc = fma2(sf2[4], w[4], acc);
                acc = fma2(sf2[5], w[5], acc);
                acc = fma2(sf2[6], w[6], acc);
                acc = fma2(sf2[7], w[7], acc);
                float2 uv = unpack2(acc);
                sSelf[sl][32] = uv.x + uv.y;
            }
        }
        __syncwarp();

        const float* bufp = &snb[par][0];

        // ---- main: per node, per k: broadcast nb row, private dot, local hsum ----
#pragma unroll
        for (int nd = 0; nd < 4; nd++) {
            const int sl = wrp * 4 + nd;
            float dk[16];
            dk[0]  = dq0.x; dk[1]  = dq0.y; dk[2]  = dq0.z; dk[3]  = dq0.w;
            dk[4]  = dq1.x; dk[5]  = dq1.y; dk[6]  = dq1.z; dk[7]  = dq1.w;
            dk[8]  = dq2.x; dk[9]  = dq2.y; dk[10] = dq2.z; dk[11] = dq2.w;
            dk[12] = dq3.x; dk[13] = dq3.y; dk[14] = dq3.z; dk[15] = dq3.w;
            if (nd < 3) {
                const float4* dp = reinterpret_cast<const float4*>(
                    dists + (size_t)(j * NPB + sl + 1) * KK);
                dq0 = dp[0]; dq1 = dp[1]; dq2 = dp[2]; dq3 = dp[3];
            }
            const float base = sSelf[sl][lane];      // lane-distinct, stride 33: conflict-free
            const float* nb = bufp + sl * NODE_FLOATS;
            float hsum = 0.0f;
#pragma unroll
            for (int kk2 = 0; kk2 < KK; kk2++) {
                ulonglong2 a0 = *reinterpret_cast<const ulonglong2*>(nb + kk2 * 4);
                ulonglong2 a1 = *reinterpret_cast<const ulonglong2*>(nb + 64 + kk2 * 4);
                ulonglong2 a2 = *reinterpret_cast<const ulonglong2*>(nb + 128 + kk2 * 4);
                ulonglong2 a3 = *reinterpret_cast<const ulonglong2*>(nb + 192 + kk2 * 4);
                u64 acc = fma2(a0.x, wA.x, 0ull);
                acc = fma2(a0.y, wA.y, acc);
                acc = fma2(a1.x, wB.x, acc);
                acc = fma2(a1.y, wB.y, acc);
                acc = fma2(a2.x, wC.x, acc);
                acc = fma2(a2.y, wC.y, acc);
                acc = fma2(a3.x, wD.x, acc);
                acc = fma2(a3.y, wD.y, acc);
                float2 uv = unpack2(acc);
                float pre = uv.x + uv.y + fmaf(dk[kk2], wdist, base);
                hsum += leaky(pre);
            }
            sHsum[sl][lane] = hsum;                  // lane-distinct, stride 36: conflict-free
        }

        // ---- g = 32 side pass (edge-parallel, 2 nodes per pass) ----
        {
            const ulonglong2 v0 = *reinterpret_cast<const ulonglong2*>(&sW1T[32][16]);
            const ulonglong2 v1 = *reinterpret_cast<const ulonglong2*>(&sW1T[32][20]);
            const ulonglong2 v2 = *reinterpret_cast<const ulonglong2*>(&sW1T[32][24]);
            const ulonglong2 v3 = *reinterpret_cast<const ulonglong2*>(&sW1T[32][28]);
            const float wd32 = sW1T[32][32];
#pragma unroll
            for (int p = 0; p < 2; p++) {
                int sl = wrp * 4 + p * 2 + half;
                int n = j * NPB + sl;
                const float* nb = bufp + sl * NODE_FLOATS + k * 4;
                ulonglong2 a0 = *reinterpret_cast<const ulonglong2*>(nb);
                ulonglong2 a1 = *reinterpret_cast<const ulonglong2*>(nb + 64);
                ulonglong2 a2 = *reinterpret_cast<const ulonglong2*>(nb + 128);
                ulonglong2 a3 = *reinterpret_cast<const ulonglong2*>(nb + 192);
                u64 acc = fma2(a0.x, v0.x, 0ull);
                acc = fma2(a0.y, v0.y, acc);
                acc = fma2(a1.x, v1.x, acc);
                acc = fma2(a1.y, v1.y, acc);
                acc = fma2(a2.x, v2.x, acc);
                acc = fma2(a2.y, v2.y, acc);
                acc = fma2(a3.x, v3.x, acc);
                acc = fma2(a3.y, v3.y, acc);
                float dkk = dists[(size_t)n * KK + k];
                float2 uv = unpack2(acc);
                float h = leaky(uv.x + uv.y + fmaf(dkk, wd32, sSelf[sl][32]));
                h += __shfl_xor_sync(0xffffffffu, h, 1);
                h += __shfl_xor_sync(0xffffffffu, h, 2);
                h += __shfl_xor_sync(0xffffffffu, h, 4);
                h += __shfl_xor_sync(0xffffffffu, h, 8);
                if (k == 0) sHsum[sl][32] = h;
            }
        }
        __syncwarp();

        // ---- epilogue: msg = 16*b2 + hsum @ W2 (lane owns channel d=k) ----
        {
            const float* w2r = &sW2T[k][0];
            const float* hsA = &sHsum[slA][0];
            const float* hsB = &sHsum[slB][0];
            float mA = 16.0f * sb2[k];
            float mB = mA;
#pragma unroll
            for (int jj = 0; jj < 8; jj++) {
                float4 w  = *reinterpret_cast<const float4*>(w2r + 4 * jj);
                float4 ha = *reinterpret_cast<const float4*>(hsA + 4 * jj);
                float4 hb = *reinterpret_cast<const float4*>(hsB + 4 * jj);
                mA += ha.x * w.x + ha.y * w.y + ha.z * w.z + ha.w * w.w;
                mB += hb.x * w.x + hb.y * w.y + hb.z * w.z + hb.w * w.w;
            }
            mA = fmaf(hsA[32], w2r[32], mA);
            mB = fmaf(hsB[32], w2r[32], mB);

            // GroupNorm stats over the 8-lane channel group (d 0-7 | 8-15)
            float muA = mA, m2A = mA * mA;
            float muB = mB, m2B = mB * mB;
#pragma unroll
            for (int off = 1; off < 8; off <<= 1) {
                muA += __shfl_xor_sync(0xffffffffu, muA, off);
                m2A += __shfl_xor_sync(0xffffffffu, m2A, off);
                muB += __shfl_xor_sync(0xffffffffu, muB, off);
                m2B += __shfl_xor_sync(0xffffffffu, m2B, off);
            }
            muA *= 0.125f; muB *= 0.125f;
            float invA = rsqrtf(fmaf(-muA, muA, m2A * 0.125f) + GN_EPS);
            float invB = rsqrtf(fmaf(-muB, muB, m2B * 0.125f) + GN_EPS);
            float oA = in_feat[(size_t)nA * DD + k] +
                       leaky(fmaf((mA - muA) * invA, sgnw[k], sgnb[k]));
            float oB = in_feat[(size_t)nB * DD + k] +
                       leaky(fmaf((mB - muB) * invB, sgnw[k], sgnb[k]));
            out_feat[(size_t)nA * DD + k] = oA;
            out_feat[(size_t)nB * DD + k] = oB;
        }

        par ^= 1;
        j = nxt;
    }
}

extern "C" void kernel_launch(void* const* d_in, const int* in_sizes, int n_in,
                              void* d_out, int out_size) {
    const float* y     = (const float*)d_in[0];
    const float* dists = (const float*)d_in[1];
    const float* W1    = (const float*)d_in[2];
    const float* b1    = (const float*)d_in[3];
    const float* W2    = (const float*)d_in[4];
    const float* b2    = (const float*)d_in[5];
    const float* gnw   = (const float*)d_in[6];
    const float* gnb   = (const float*)d_in[7];
    const void*  idx   = (const void*)d_in[8];
    float* out = (float*)d_out;

    float *buf0, *buf1;
    int* idx32;
    cudaGetSymbolAddress((void**)&buf0, g_buf0);
    cudaGetSymbolAddress((void**)&buf1, g_buf1);
    cudaGetSymbolAddress((void**)&idx32, g_idx32);

    detect_idx_kernel<<<1, 1>>>((const long long*)idx);
    convert_idx_kernel<<<(NN * KK + 255) / 256, 256>>>(idx);

    layer_kernel<<<GRIDB, 128>>>(y,    dists, idx32, W1,               b1,          W2,               b2,          gnw,          gnb,          buf0);
    layer_kernel<<<GRIDB, 128>>>(buf0, dists, idx32, W1 + 1 * FF * FF, b1 + 1 * FF, W2 + 1 * FF * DD, b2 + 1 * DD, gnw + 1 * DD, gnb + 1 * DD, buf1);
    layer_kernel<<<GRIDB, 128>>>(buf1, dists, idx32, W1 + 2 * FF * FF, b1 + 2 * FF, W2 + 2 * FF * DD, b2 + 2 * DD, gnw + 2 * DD, gnb + 2 * DD, out);
}